// round 1
// baseline (speedup 1.0000x reference)
#include <cuda_runtime.h>
#include <math.h>

#define NTOK  8192      // B*S
#define HDIM  1152
#define TOTAL (NTOK*HDIM)   // 9437184
#define SEQ   2048
#define INNERD 4608
#define NMH   4
#define HDH   96
#define MDH   128

// ---------------- scratch (device globals; no allocs allowed) ----------------
__device__ float g_x  [TOTAL];
__device__ float g_a  [TOTAL];
__device__ float g_b  [TOTAL];
__device__ float g_c  [TOTAL];
__device__ float g_d  [TOTAL];
__device__ float g_gp [NTOK*2304];
__device__ float g_ffn[NTOK*9216];
__device__ float g_glu[NTOK*INNERD];
__device__ float g_q  [NTOK*NMH*HDH];
__device__ float g_k  [NTOK*NMH*HDH];
__device__ float g_v  [NTOK*NMH*MDH];
__device__ float g_r  [NTOK*NMH*MDH];
__device__ float g_g  [NTOK*NMH];
__device__ float g_ga [4*32*NMH];
__device__ float g_gate[NTOK];
__device__ float g_hw [NTOK*12];

__constant__ int c_head_dil[12][3] = {
  {1,2,4},{1,1,1},{4,8,16},{8,16,32},{32,64,128},{64,128,256},
  {256,512,1024},{1,100,200},{1,500,1000},{1,1024,2048},{3,9,27},{5,25,125}
};

__device__ __forceinline__ float sigmoidf_(float x){ return 1.f/(1.f+__expf(-x)); }

// ---------------- fused rmsnorm + token scalar gate ----------------
__global__ void rms_gate_kernel(const float* __restrict__ x, const float* __restrict__ nw,
                                const float* __restrict__ gw, const float* __restrict__ gb,
                                float* __restrict__ xn, float* __restrict__ gate)
{
    __shared__ float s1[8], s2[8], sinv;
    int t = blockIdx.x;
    const float* xr = x + (long)t*HDIM;
    float ss=0.f, dg=0.f;
    for (int c=threadIdx.x; c<HDIM; c+=256){ float v=xr[c]; ss+=v*v; dg+=v*gw[c]; }
    for (int o=16;o;o>>=1){ ss+=__shfl_down_sync(~0u,ss,o); dg+=__shfl_down_sync(~0u,dg,o); }
    int w=threadIdx.x>>5, l=threadIdx.x&31;
    if (l==0){ s1[w]=ss; s2[w]=dg; }
    __syncthreads();
    if (threadIdx.x==0){
        float a=0,bq=0;
        #pragma unroll
        for (int i=0;i<8;i++){ a+=s1[i]; bq+=s2[i]; }
        sinv = rsqrtf(a/(float)HDIM + 1e-6f);
        gate[t] = 1.f/(1.f+expf(-(bq+gb[0])));
    }
    __syncthreads();
    float inv = sinv;
    for (int c=threadIdx.x; c<HDIM; c+=256) xn[(long)t*HDIM+c] = xr[c]*inv*nw[c];
}

// ---------------- conv stack layer: out = in + gelu(bias + sum w*taps) ----------------
__global__ void conv_cs_kernel(const float* __restrict__ in, float* __restrict__ out,
                               const float* __restrict__ w, const float* __restrict__ bias, int d)
{
    int idx = blockIdx.x*256 + threadIdx.x;
    if (idx >= TOTAL) return;
    int c = idx % HDIM;
    int t = idx / HDIM;
    int s = t & (SEQ-1);
    float acc = bias[c];
    const float* wc = w + c*4;
    #pragma unroll
    for (int j=0;j<4;j++){
        int sp = s - (3-j)*d;
        if (sp >= 0) acc += wc[j] * in[idx + (sp - s)*HDIM];
    }
    float g = 0.5f*acc*(1.f + erff(acc*0.70710678118654752f));
    out[idx] = in[idx] + g;
}

// ---------------- head conv layer (all 12 heads, per-head dilation) ----------------
__global__ void conv_head_kernel(const float* __restrict__ in, float* __restrict__ out,
                                 const float* __restrict__ hw, const float* __restrict__ hb, int layer)
{
    int idx = blockIdx.x*256 + threadIdx.x;
    if (idx >= TOTAL) return;
    int ch = idx % HDIM;
    int i  = ch / HDH;
    int c  = ch % HDH;
    int t  = idx / HDIM;
    int s  = t & (SEQ-1);
    int d  = c_head_dil[i][layer];
    int wb = (i*3 + layer)*HDH + c;
    const float* wc = hw + wb*4;
    float acc = hb[wb];
    #pragma unroll
    for (int j=0;j<4;j++){
        int sp = s - (3-j)*d;
        if (sp >= 0) acc += wc[j] * in[idx + (sp - s)*HDIM];
    }
    out[idx] = in[idx] + acc;
}

// ---------------- elementwise ----------------
__global__ void glu_kernel(const float* __restrict__ in, float* __restrict__ out, int half, int total)
{
    int idx = blockIdx.x*256 + threadIdx.x;
    if (idx >= total) return;
    int t = idx / half, c = idx % half;
    float a = in[t*2*half + c];
    float bq = in[t*2*half + half + c];
    out[idx] = a * sigmoidf_(bq);
}

__global__ void resid_kernel(const float* __restrict__ base, const float* __restrict__ y,
                             const float* __restrict__ gate, float* __restrict__ out)
{
    int idx = blockIdx.x*256 + threadIdx.x;
    if (idx >= TOTAL) return;
    out[idx] = base[idx] + gate[idx/HDIM]*y[idx];
}

__global__ void mulsig_kernel(float* __restrict__ a, const float* __restrict__ z)
{
    int idx = blockIdx.x*256 + threadIdx.x;
    if (idx >= TOTAL) return;
    a[idx] *= sigmoidf_(z[idx]);
}

__global__ void hwmul_kernel(float* __restrict__ a, const float* __restrict__ hw)
{
    int idx = blockIdx.x*256 + threadIdx.x;
    if (idx >= TOTAL) return;
    int t = idx / HDIM, h = (idx % HDIM)/HDH;
    a[idx] *= hw[t*12 + h];
}

// ---------------- memory-head gate g and chunk means ----------------
__global__ void memg_kernel(const float* __restrict__ xg, const float* __restrict__ gw,
                            const float* __restrict__ gb, float* __restrict__ g)
{
    int t = blockIdx.x;
    int warp = threadIdx.x >> 5, lane = threadIdx.x & 31;
    const float* xr = xg + (long)t*HDIM + (6+warp)*HDH;
    const float* w  = gw + warp*HDH;
    float acc = 0.f;
    for (int c=lane;c<HDH;c+=32) acc += xr[c]*w[c];
    for (int o=16;o;o>>=1) acc += __shfl_down_sync(~0u,acc,o);
    if (lane==0) g[t*NMH+warp] = 1.f/(1.f+expf(-(acc + gb[warp])));
}

__global__ void ga_kernel(const float* __restrict__ g, float* __restrict__ ga)
{
    int e = blockIdx.x*256 + threadIdx.x;
    if (e >= 4*32*NMH) return;
    int n = e % NMH, ch = (e/NMH) % 32, b = e/(NMH*32);
    int base = (b*SEQ + ch*64)*NMH + n;
    float s = 0.f;
    for (int i=0;i<64;i++) s += g[base + i*NMH];
    ga[e] = s*(1.f/64.f);
}

// ---------------- chunked fast-weight scan (column-split over MD) ----------------
// grid (B*NM, MD/32), 256 threads, dyn smem 69632 B
__global__ void scan_kernel(const float* __restrict__ q, const float* __restrict__ kk,
                            const float* __restrict__ v, const float* __restrict__ g,
                            const float* __restrict__ ga, float* __restrict__ reads)
{
    extern __shared__ float sm[];
    float* sM = sm;              // 96*32
    float* sQ = sM + 96*32;      // 64*96
    float* sK = sQ + 64*96;      // 64*96 (k*g)
    float* sV = sK + 64*96;      // 64*32
    int bn = blockIdx.x;
    int b = bn >> 2, n = bn & 3;
    int m0 = blockIdx.y * 32;
    int tid = threadIdx.x;
    for (int i=tid;i<96*32;i+=256) sM[i]=0.f;
    __syncthreads();
    for (int ch=0; ch<32; ch++){
        int tok0 = b*SEQ + ch*64;
        for (int i=tid;i<64*96;i+=256){
            int s = i/96, dd = i%96;
            int gi = (tok0+s)*(NMH*HDH) + n*HDH + dd;
            sQ[i] = q[gi];
            sK[i] = kk[gi] * g[(tok0+s)*NMH + n];
        }
        for (int i=tid;i<64*32;i+=256){
            int s=i/32, m=i%32;
            sV[i] = v[(tok0+s)*(NMH*MDH) + n*MDH + m0 + m];
        }
        __syncthreads();
        // reads with OLD M
        for (int o=tid;o<64*32;o+=256){
            int s=o/32, m=o%32;
            float acc=0.f;
            const float* qs = sQ + s*96;
            #pragma unroll 8
            for (int dd=0; dd<96; dd++) acc += qs[dd]*sM[dd*32+m];
            reads[(tok0+s)*(NMH*MDH) + n*MDH + m0 + m] = acc;
        }
        __syncthreads();
        float gav = ga[(b*32+ch)*NMH + n];
        for (int e=tid;e<96*32;e+=256){
            int dd=e/32, m=e%32;
            float acc = (1.f-gav)*sM[e];
            #pragma unroll 8
            for (int s=0;s<64;s++) acc += sK[s*96+dd]*sV[s*32+m];
            sM[e]=acc;
        }
        __syncthreads();
    }
}

// ---------------- generic fp32 GEMM: C = act(A@B [+bias] [+C]) ----------------
// 128x128x8 tiles, 256 threads, 8x8 microtile. Assumes M%128==0, K%8==0, N%4==0.
template<bool BIAS, bool ACC, int ACT>
__global__ __launch_bounds__(256) void sgemm(
    const float* __restrict__ A, const float* __restrict__ B,
    const float* __restrict__ bias, float* __restrict__ C,
    int M, int N, int K, int lda, int ldb, int ldc,
    long sA, long sB, long sC)
{
    __shared__ __align__(16) float As[8*128];
    __shared__ __align__(16) float Bs[8*128];
    A += (long)blockIdx.z * sA;
    B += (long)blockIdx.z * sB;
    C += (long)blockIdx.z * sC;
    int tid = threadIdx.x;
    int row0 = blockIdx.y * 128;
    int col0 = blockIdx.x * 128;
    int tr4 = (tid >> 4) * 4;
    int tc4 = (tid & 15) * 4;
    int arow = tid >> 1, acol = (tid & 1) * 4;
    int brow = tid >> 5, bcol = (tid & 31) * 4;
    const float* Aptr = A + (long)(row0 + arow)*lda + acol;
    const float* Bptr = B + (long)brow*ldb + col0 + bcol;
    bool bvalid = (col0 + bcol + 3) < N;
    float acc[8][8];
    #pragma unroll
    for (int i=0;i<8;i++)
        #pragma unroll
        for (int j=0;j<8;j++) acc[i][j]=0.f;

    for (int k0=0;k0<K;k0+=8){
        float4 av = *(const float4*)Aptr;
        As[(acol+0)*128 + arow]=av.x;
        As[(acol+1)*128 + arow]=av.y;
        As[(acol+2)*128 + arow]=av.z;
        As[(acol+3)*128 + arow]=av.w;
        float4 bv = bvalid ? *(const float4*)Bptr : make_float4(0.f,0.f,0.f,0.f);
        *(float4*)&Bs[brow*128 + bcol] = bv;
        __syncthreads();
        #pragma unroll
        for (int k=0;k<8;k++){
            float4 a0 = *(const float4*)&As[k*128 + tr4];
            float4 a1 = *(const float4*)&As[k*128 + tr4 + 64];
            float4 b0 = *(const float4*)&Bs[k*128 + tc4];
            float4 b1 = *(const float4*)&Bs[k*128 + tc4 + 64];
            float ra[8] = {a0.x,a0.y,a0.z,a0.w,a1.x,a1.y,a1.z,a1.w};
            float rb[8] = {b0.x,b0.y,b0.z,b0.w,b1.x,b1.y,b1.z,b1.w};
            #pragma unroll
            for (int i=0;i<8;i++)
                #pragma unroll
                for (int j=0;j<8;j++) acc[i][j] += ra[i]*rb[j];
        }
        __syncthreads();
        Aptr += 8;
        Bptr += 8*(long)ldb;
    }
    #pragma unroll
    for (int i=0;i<8;i++){
        int r = row0 + tr4 + (i<4 ? i : i-4+64);
        #pragma unroll
        for (int j=0;j<8;j++){
            int cN = col0 + tc4 + (j<4 ? j : j-4+64);
            if (cN < N){
                float v = acc[i][j];
                if (BIAS) v += bias[cN];
                if (ACC)  v += C[(long)r*ldc + cN];
                if (ACT==1) v = 1.f/(1.f+expf(-v));
                C[(long)r*ldc + cN] = v;
            }
        }
    }
}

// ---------------- host ----------------
extern "C" void kernel_launch(void* const* d_in, const int* in_sizes, int n_in,
                              void* d_out, int out_size)
{
    const float* x          = (const float*)d_in[0];
    const float* norm1_w    = (const float*)d_in[1];
    const float* norm2_w    = (const float*)d_in[2];
    const float* norm3_w    = (const float*)d_in[3];
    const float* cs_w       = (const float*)d_in[4];
    const float* cs_b       = (const float*)d_in[5];
    const float* cs_proj_w  = (const float*)d_in[6];
    const float* cs_proj_b  = (const float*)d_in[7];
    const float* gate_proj_w= (const float*)d_in[8];
    const float* router_w   = (const float*)d_in[9];
    const float* router_b   = (const float*)d_in[10];
    const float* head_w     = (const float*)d_in[11];
    const float* head_b     = (const float*)d_in[12];
    const float* mem_q      = (const float*)d_in[13];
    const float* mem_k      = (const float*)d_in[14];
    const float* mem_v      = (const float*)d_in[15];
    const float* mem_gw     = (const float*)d_in[16];
    const float* mem_gb     = (const float*)d_in[17];
    const float* mem_out    = (const float*)d_in[18];
    const float* mixgate_w  = (const float*)d_in[19];
    const float* mixgate_b  = (const float*)d_in[20];
    const float* mixing_w   = (const float*)d_in[21];
    const float* mixing_b   = (const float*)d_in[22];
    const float* ffn_in_w   = (const float*)d_in[23];
    const float* ffn_out_w  = (const float*)d_in[24];
    const float* cg_w       = (const float*)d_in[25];
    const float* cg_b       = (const float*)d_in[26];
    const float* sg_w       = (const float*)d_in[27];
    const float* sg_b       = (const float*)d_in[28];
    const float* fg_w       = (const float*)d_in[29];
    const float* fg_b       = (const float*)d_in[30];

    float *X,*A,*Bb,*C,*D,*GP,*FFN,*GLU,*Q,*Kb,*V,*R,*G,*GA,*GATE,*HW;
    cudaGetSymbolAddress((void**)&X,  g_x);
    cudaGetSymbolAddress((void**)&A,  g_a);
    cudaGetSymbolAddress((void**)&Bb, g_b);
    cudaGetSymbolAddress((void**)&C,  g_c);
    cudaGetSymbolAddress((void**)&D,  g_d);
    cudaGetSymbolAddress((void**)&GP, g_gp);
    cudaGetSymbolAddress((void**)&FFN,g_ffn);
    cudaGetSymbolAddress((void**)&GLU,g_glu);
    cudaGetSymbolAddress((void**)&Q,  g_q);
    cudaGetSymbolAddress((void**)&Kb, g_k);
    cudaGetSymbolAddress((void**)&V,  g_v);
    cudaGetSymbolAddress((void**)&R,  g_r);
    cudaGetSymbolAddress((void**)&G,  g_g);
    cudaGetSymbolAddress((void**)&GA, g_ga);
    cudaGetSymbolAddress((void**)&GATE,g_gate);
    cudaGetSymbolAddress((void**)&HW, g_hw);

    cudaFuncSetAttribute(scan_kernel, cudaFuncAttributeMaxDynamicSharedMemorySize, 69632);

    const int EB = 36864; // TOTAL/256

    // ===== stage 1: conv stack =====
    rms_gate_kernel<<<NTOK,256>>>(x, norm1_w, cg_w, cg_b, A, GATE);
    {
        const int dil[6] = {1,2,4,8,16,32};
        float* pin = A; float* pout = Bb;
        for (int i=0;i<6;i++){
            conv_cs_kernel<<<EB,256>>>(pin, pout, cs_w + i*HDIM*4, cs_b + i*HDIM, dil[i]);
            float* tmp = pin; pin = pout; pout = tmp;
        }
        // 6 layers -> result back in A
    }
    sgemm<true,false,0><<<dim3(9,64,1),256>>>(A, cs_proj_w, cs_proj_b, C,
        NTOK, HDIM, HDIM, HDIM, HDIM, HDIM, 0,0,0);
    resid_kernel<<<EB,256>>>(x, C, GATE, X);

    // ===== stage 2: multi-head state =====
    rms_gate_kernel<<<NTOK,256>>>(X, norm2_w, sg_w, sg_b, A, GATE);
    sgemm<true,false,1><<<dim3(1,64,1),256>>>(A, router_w, router_b, HW,
        NTOK, 12, HDIM, HDIM, 12, 12, 0,0,0);
    sgemm<false,false,0><<<dim3(18,64,1),256>>>(A, gate_proj_w, nullptr, GP,
        NTOK, 2304, HDIM, HDIM, 2304, 2304, 0,0,0);
    glu_kernel<<<EB,256>>>(GP, Bb, HDIM, TOTAL);
    memg_kernel<<<NTOK,128>>>(Bb, mem_gw, mem_gb, G);
    ga_kernel<<<2,256>>>(G, GA);
    // batched q/k/v projections over 4 memory heads
    sgemm<false,false,0><<<dim3(1,64,4),256>>>(Bb + 6*HDH, mem_q, nullptr, Q,
        NTOK, HDH, HDH, HDIM, HDH, NMH*HDH, HDH, HDH*HDH, HDH);
    sgemm<false,false,0><<<dim3(1,64,4),256>>>(Bb + 6*HDH, mem_k, nullptr, Kb,
        NTOK, HDH, HDH, HDIM, HDH, NMH*HDH, HDH, HDH*HDH, HDH);
    sgemm<false,false,0><<<dim3(1,64,4),256>>>(Bb + 6*HDH, mem_v, nullptr, V,
        NTOK, MDH, HDH, HDIM, MDH, NMH*MDH, HDH, HDH*MDH, MDH);
    // per-head dilated convs (3 layers, all 12 heads each)
    conv_head_kernel<<<EB,256>>>(Bb, C, head_w, head_b, 0);
    conv_head_kernel<<<EB,256>>>(C,  A, head_w, head_b, 1);
    conv_head_kernel<<<EB,256>>>(A,  C, head_w, head_b, 2);
    // fast-weight scan
    scan_kernel<<<dim3(16,4),256,69632>>>(Q, Kb, V, G, GA, R);
    // mem output projection, accumulated into the 4 memory heads
    sgemm<false,true,0><<<dim3(1,64,4),256>>>(R, mem_out, nullptr, C + 6*HDH,
        NTOK, HDH, MDH, NMH*MDH, HDH, HDIM, MDH, MDH*HDH, HDH);
    hwmul_kernel<<<EB,256>>>(C, HW);
    sgemm<true,false,0><<<dim3(9,64,1),256>>>(C, mixgate_w, mixgate_b, D,
        NTOK, HDIM, HDIM, HDIM, HDIM, HDIM, 0,0,0);
    mulsig_kernel<<<EB,256>>>(C, D);
    sgemm<true,false,0><<<dim3(9,64,1),256>>>(C, mixing_w, mixing_b, D,
        NTOK, HDIM, HDIM, HDIM, HDIM, HDIM, 0,0,0);
    resid_kernel<<<EB,256>>>(X, D, GATE, X);

    // ===== stage 3: GLU FFN =====
    rms_gate_kernel<<<NTOK,256>>>(X, norm3_w, fg_w, fg_b, A, GATE);
    sgemm<false,false,0><<<dim3(72,64,1),256>>>(A, ffn_in_w, nullptr, FFN,
        NTOK, 9216, HDIM, HDIM, 9216, 9216, 0,0,0);
    glu_kernel<<<(NTOK*INNERD+255)/256,256>>>(FFN, GLU, INNERD, NTOK*INNERD);
    sgemm<false,false,0><<<dim3(9,64,1),256>>>(GLU, ffn_out_w, nullptr, C,
        NTOK, HDIM, INNERD, INNERD, HDIM, HDIM, 0,0,0);
    resid_kernel<<<EB,256>>>(X, C, GATE, (float*)d_out);

    (void)in_sizes; (void)n_in; (void)out_size;
}

// round 2
// speedup vs baseline: 2.1828x; 2.1828x over previous
#include <cuda_runtime.h>
#include <math.h>
#include <stdint.h>

#define NTOK  8192      // B*S
#define HDIM  1152
#define TOTAL (NTOK*HDIM)   // 9437184
#define SEQ   2048
#define INNERD 4608
#define NMH   4
#define HDH   96
#define MDH   128

// ---------------- scratch (device globals; no allocs allowed) ----------------
__device__ float g_x  [TOTAL];
__device__ float g_a  [TOTAL];
__device__ float g_b  [TOTAL];
__device__ float g_c  [TOTAL];
__device__ float g_d  [TOTAL];
__device__ float g_gp [NTOK*2304];
__device__ float g_ffn[NTOK*9216];
__device__ float g_glu[NTOK*INNERD];
__device__ float g_q  [NTOK*NMH*HDH];
__device__ float g_k  [NTOK*NMH*HDH];
__device__ float g_v  [NTOK*NMH*MDH];
__device__ float g_r  [NTOK*NMH*MDH];
__device__ float g_g  [NTOK*NMH];
__device__ float g_ga [4*32*NMH];
__device__ float g_gate[NTOK];
__device__ float g_hw [NTOK*12];

__constant__ int c_head_dil[12][3] = {
  {1,2,4},{1,1,1},{4,8,16},{8,16,32},{32,64,128},{64,128,256},
  {256,512,1024},{1,100,200},{1,500,1000},{1,1024,2048},{3,9,27},{5,25,125}
};

__device__ __forceinline__ float sigmoidf_(float x){ return 1.f/(1.f+__expf(-x)); }
__device__ __forceinline__ float f2tf32(float f){
    uint32_t r; asm("cvt.rna.tf32.f32 %0,%1;" : "=r"(r) : "f"(f));
    return __uint_as_float(r);
}

// ---------------- fused rmsnorm + token scalar gate ----------------
__global__ void rms_gate_kernel(const float* __restrict__ x, const float* __restrict__ nw,
                                const float* __restrict__ gw, const float* __restrict__ gb,
                                float* __restrict__ xn, float* __restrict__ gate)
{
    __shared__ float s1[8], s2[8], sinv;
    int t = blockIdx.x;
    const float* xr = x + (long)t*HDIM;
    float ss=0.f, dg=0.f;
    for (int c=threadIdx.x; c<HDIM; c+=256){ float v=xr[c]; ss+=v*v; dg+=v*gw[c]; }
    for (int o=16;o;o>>=1){ ss+=__shfl_down_sync(~0u,ss,o); dg+=__shfl_down_sync(~0u,dg,o); }
    int w=threadIdx.x>>5, l=threadIdx.x&31;
    if (l==0){ s1[w]=ss; s2[w]=dg; }
    __syncthreads();
    if (threadIdx.x==0){
        float a=0,bq=0;
        #pragma unroll
        for (int i=0;i<8;i++){ a+=s1[i]; bq+=s2[i]; }
        sinv = rsqrtf(a/(float)HDIM + 1e-6f);
        gate[t] = 1.f/(1.f+expf(-(bq+gb[0])));
    }
    __syncthreads();
    float inv = sinv;
    for (int c=threadIdx.x; c<HDIM; c+=256) xn[(long)t*HDIM+c] = xr[c]*inv*nw[c];
}

// ---------------- conv stack layer ----------------
__global__ void conv_cs_kernel(const float* __restrict__ in, float* __restrict__ out,
                               const float* __restrict__ w, const float* __restrict__ bias, int d)
{
    int idx = blockIdx.x*256 + threadIdx.x;
    if (idx >= TOTAL) return;
    int c = idx % HDIM;
    int t = idx / HDIM;
    int s = t & (SEQ-1);
    float acc = bias[c];
    const float* wc = w + c*4;
    #pragma unroll
    for (int j=0;j<4;j++){
        int sp = s - (3-j)*d;
        if (sp >= 0) acc += wc[j] * in[idx + (sp - s)*HDIM];
    }
    float g = 0.5f*acc*(1.f + erff(acc*0.70710678118654752f));
    out[idx] = in[idx] + g;
}

// ---------------- head conv layer ----------------
__global__ void conv_head_kernel(const float* __restrict__ in, float* __restrict__ out,
                                 const float* __restrict__ hw, const float* __restrict__ hb, int layer)
{
    int idx = blockIdx.x*256 + threadIdx.x;
    if (idx >= TOTAL) return;
    int ch = idx % HDIM;
    int i  = ch / HDH;
    int c  = ch % HDH;
    int t  = idx / HDIM;
    int s  = t & (SEQ-1);
    int d  = c_head_dil[i][layer];
    int wb = (i*3 + layer)*HDH + c;
    const float* wc = hw + wb*4;
    float acc = hb[wb];
    #pragma unroll
    for (int j=0;j<4;j++){
        int sp = s - (3-j)*d;
        if (sp >= 0) acc += wc[j] * in[idx + (sp - s)*HDIM];
    }
    out[idx] = in[idx] + acc;
}

// ---------------- elementwise ----------------
__global__ void glu_kernel(const float* __restrict__ in, float* __restrict__ out, int half, int total)
{
    int idx = blockIdx.x*256 + threadIdx.x;
    if (idx >= total) return;
    int t = idx / half, c = idx % half;
    float a = in[t*2*half + c];
    float bq = in[t*2*half + half + c];
    out[idx] = a * sigmoidf_(bq);
}

__global__ void resid_kernel(const float* __restrict__ base, const float* __restrict__ y,
                             const float* __restrict__ gate, float* __restrict__ out)
{
    int idx = blockIdx.x*256 + threadIdx.x;
    if (idx >= TOTAL) return;
    out[idx] = base[idx] + gate[idx/HDIM]*y[idx];
}

__global__ void mulsig_kernel(float* __restrict__ a, const float* __restrict__ z)
{
    int idx = blockIdx.x*256 + threadIdx.x;
    if (idx >= TOTAL) return;
    a[idx] *= sigmoidf_(z[idx]);
}

__global__ void hwmul_kernel(float* __restrict__ a, const float* __restrict__ hw)
{
    int idx = blockIdx.x*256 + threadIdx.x;
    if (idx >= TOTAL) return;
    int t = idx / HDIM, h = (idx % HDIM)/HDH;
    a[idx] *= hw[t*12 + h];
}

// ---------------- memory-head gate g and chunk means ----------------
__global__ void memg_kernel(const float* __restrict__ xg, const float* __restrict__ gw,
                            const float* __restrict__ gb, float* __restrict__ g)
{
    int t = blockIdx.x;
    int warp = threadIdx.x >> 5, lane = threadIdx.x & 31;
    const float* xr = xg + (long)t*HDIM + (6+warp)*HDH;
    const float* w  = gw + warp*HDH;
    float acc = 0.f;
    for (int c=lane;c<HDH;c+=32) acc += xr[c]*w[c];
    for (int o=16;o;o>>=1) acc += __shfl_down_sync(~0u,acc,o);
    if (lane==0) g[t*NMH+warp] = 1.f/(1.f+expf(-(acc + gb[warp])));
}

__global__ void ga_kernel(const float* __restrict__ g, float* __restrict__ ga)
{
    int e = blockIdx.x*256 + threadIdx.x;
    if (e >= 4*32*NMH) return;
    int n = e % NMH, ch = (e/NMH) % 32, b = e/(NMH*32);
    int base = (b*SEQ + ch*64)*NMH + n;
    float s = 0.f;
    for (int i=0;i<64;i++) s += g[base + i*NMH];
    ga[e] = s*(1.f/64.f);
}

// ---------------- chunked fast-weight scan ----------------
__global__ void scan_kernel(const float* __restrict__ q, const float* __restrict__ kk,
                            const float* __restrict__ v, const float* __restrict__ g,
                            const float* __restrict__ ga, float* __restrict__ reads)
{
    extern __shared__ float sm[];
    float* sM = sm;              // 96*32
    float* sQ = sM + 96*32;      // 64*96
    float* sK = sQ + 64*96;      // 64*96
    float* sV = sK + 64*96;      // 64*32
    int bn = blockIdx.x;
    int b = bn >> 2, n = bn & 3;
    int m0 = blockIdx.y * 32;
    int tid = threadIdx.x;
    for (int i=tid;i<96*32;i+=256) sM[i]=0.f;
    __syncthreads();
    for (int ch=0; ch<32; ch++){
        int tok0 = b*SEQ + ch*64;
        for (int i=tid;i<64*96;i+=256){
            int s = i/96, dd = i%96;
            int gi = (tok0+s)*(NMH*HDH) + n*HDH + dd;
            sQ[i] = q[gi];
            sK[i] = kk[gi] * g[(tok0+s)*NMH + n];
        }
        for (int i=tid;i<64*32;i+=256){
            int s=i/32, m=i%32;
            sV[i] = v[(tok0+s)*(NMH*MDH) + n*MDH + m0 + m];
        }
        __syncthreads();
        for (int o=tid;o<64*32;o+=256){
            int s=o/32, m=o%32;
            float acc=0.f;
            const float* qs = sQ + s*96;
            #pragma unroll 8
            for (int dd=0; dd<96; dd++) acc += qs[dd]*sM[dd*32+m];
            reads[(tok0+s)*(NMH*MDH) + n*MDH + m0 + m] = acc;
        }
        __syncthreads();
        float gav = ga[(b*32+ch)*NMH + n];
        for (int e=tid;e<96*32;e+=256){
            int dd=e/32, m=e%32;
            float acc = (1.f-gav)*sM[e];
            #pragma unroll 8
            for (int s=0;s<64;s++) acc += sK[s*96+dd]*sV[s*32+m];
            sM[e]=acc;
        }
        __syncthreads();
    }
}

// ---------------- SIMT fp32 GEMM (small-N cases: router) ----------------
template<bool BIAS, bool ACC, int ACT>
__global__ __launch_bounds__(256) void sgemm(
    const float* __restrict__ A, const float* __restrict__ B,
    const float* __restrict__ bias, float* __restrict__ C,
    int M, int N, int K, int lda, int ldb, int ldc,
    long sA, long sB, long sC)
{
    __shared__ __align__(16) float As[8*128];
    __shared__ __align__(16) float Bs[8*128];
    A += (long)blockIdx.z * sA;
    B += (long)blockIdx.z * sB;
    C += (long)blockIdx.z * sC;
    int tid = threadIdx.x;
    int row0 = blockIdx.y * 128;
    int col0 = blockIdx.x * 128;
    int tr4 = (tid >> 4) * 4;
    int tc4 = (tid & 15) * 4;
    int arow = tid >> 1, acol = (tid & 1) * 4;
    int brow = tid >> 5, bcol = (tid & 31) * 4;
    const float* Aptr = A + (long)(row0 + arow)*lda + acol;
    const float* Bptr = B + (long)brow*ldb + col0 + bcol;
    bool bvalid = (col0 + bcol + 3) < N;
    float acc[8][8];
    #pragma unroll
    for (int i=0;i<8;i++)
        #pragma unroll
        for (int j=0;j<8;j++) acc[i][j]=0.f;

    for (int k0=0;k0<K;k0+=8){
        float4 av = *(const float4*)Aptr;
        As[(acol+0)*128 + arow]=av.x;
        As[(acol+1)*128 + arow]=av.y;
        As[(acol+2)*128 + arow]=av.z;
        As[(acol+3)*128 + arow]=av.w;
        float4 bv = bvalid ? *(const float4*)Bptr : make_float4(0.f,0.f,0.f,0.f);
        *(float4*)&Bs[brow*128 + bcol] = bv;
        __syncthreads();
        #pragma unroll
        for (int k=0;k<8;k++){
            float4 a0 = *(const float4*)&As[k*128 + tr4];
            float4 a1 = *(const float4*)&As[k*128 + tr4 + 64];
            float4 b0 = *(const float4*)&Bs[k*128 + tc4];
            float4 b1 = *(const float4*)&Bs[k*128 + tc4 + 64];
            float ra[8] = {a0.x,a0.y,a0.z,a0.w,a1.x,a1.y,a1.z,a1.w};
            float rb[8] = {b0.x,b0.y,b0.z,b0.w,b1.x,b1.y,b1.z,b1.w};
            #pragma unroll
            for (int i=0;i<8;i++)
                #pragma unroll
                for (int j=0;j<8;j++) acc[i][j] += ra[i]*rb[j];
        }
        __syncthreads();
        Aptr += 8;
        Bptr += 8*(long)ldb;
    }
    #pragma unroll
    for (int i=0;i<8;i++){
        int r = row0 + tr4 + (i<4 ? i : i-4+64);
        #pragma unroll
        for (int j=0;j<8;j++){
            int cN = col0 + tc4 + (j<4 ? j : j-4+64);
            if (cN < N){
                float v = acc[i][j];
                if (BIAS) v += bias[cN];
                if (ACC)  v += C[(long)r*ldc + cN];
                if (ACT==1) v = 1.f/(1.f+expf(-v));
                C[(long)r*ldc + cN] = v;
            }
        }
    }
}

// ---------------- tf32 tensor-core GEMM: C = A@B [+bias] [+C] ----------------
// 128x128x16 tiles, 256 threads = 8 warps (2Mx4N), warp tile 64x32.
// mma.sync.m16n8k8.tf32, fp32 accumulate. Double-buffered smem.
// A smem stride 20 (conflict-free frag loads), B smem stride 136.
// Requires: M%128==0, K%16==0, N%4==0.
#define AST 20
#define BST 136
template<bool BIAS, bool ACC>
__global__ __launch_bounds__(256) void tgemm(
    const float* __restrict__ A, const float* __restrict__ B,
    const float* __restrict__ bias, float* __restrict__ C,
    int M, int N, int K, int lda, int ldb, int ldc,
    long sA, long sB, long sC)
{
    __shared__ __align__(16) float As[2][128*AST];
    __shared__ __align__(16) float Bs[2][16*BST];

    A += (long)blockIdx.z * sA;
    B += (long)blockIdx.z * sB;
    C += (long)blockIdx.z * sC;

    const int tid  = threadIdx.x;
    const int lane = tid & 31;
    const int wid  = tid >> 5;
    const int wm   = (wid >> 2) * 64;   // warp M offset (0 / 64)
    const int wn   = (wid & 3) * 32;    // warp N offset
    const int qr   = lane >> 2;         // 0..7
    const int qc   = lane & 3;          // 0..3

    const int row0 = blockIdx.y * 128;
    const int col0 = blockIdx.x * 128;

    // global-load mapping
    const int ar = tid >> 2;            // 0..63 (A rows ar, ar+64)
    const int ac = (tid & 3) * 4;       // k offset within tile
    const int bk = tid >> 5;            // 0..7 (B k-rows bk, bk+8)
    const int bn = (lane) * 4;          // 0..124
    const bool bok = (col0 + bn) < N;   // N%4==0 -> whole float4 valid

    const float* Ag = A + (long)(row0 + ar)*lda + ac;
    const float* Bg = B + (long)bk*ldb + col0 + bn;

    float acc[4][4][4];
    #pragma unroll
    for (int i=0;i<4;i++)
        #pragma unroll
        for (int j=0;j<4;j++)
            #pragma unroll
            for (int e=0;e<4;e++) acc[i][j][e]=0.f;

    const int nt = K >> 4;
    float4 pa0, pa1, pb0, pb1;

    // prologue: load tile 0
    pa0 = *(const float4*)(Ag);
    pa1 = *(const float4*)(Ag + 64*(long)lda);
    pb0 = bok ? *(const float4*)(Bg)               : make_float4(0,0,0,0);
    pb1 = bok ? *(const float4*)(Bg + 8*(long)ldb) : make_float4(0,0,0,0);
    {
        float* as = As[0]; float* bs = Bs[0];
        as[ar*AST + ac+0] = f2tf32(pa0.x); as[ar*AST + ac+1] = f2tf32(pa0.y);
        as[ar*AST + ac+2] = f2tf32(pa0.z); as[ar*AST + ac+3] = f2tf32(pa0.w);
        as[(ar+64)*AST + ac+0] = f2tf32(pa1.x); as[(ar+64)*AST + ac+1] = f2tf32(pa1.y);
        as[(ar+64)*AST + ac+2] = f2tf32(pa1.z); as[(ar+64)*AST + ac+3] = f2tf32(pa1.w);
        bs[bk*BST + bn+0] = f2tf32(pb0.x); bs[bk*BST + bn+1] = f2tf32(pb0.y);
        bs[bk*BST + bn+2] = f2tf32(pb0.z); bs[bk*BST + bn+3] = f2tf32(pb0.w);
        bs[(bk+8)*BST + bn+0] = f2tf32(pb1.x); bs[(bk+8)*BST + bn+1] = f2tf32(pb1.y);
        bs[(bk+8)*BST + bn+2] = f2tf32(pb1.z); bs[(bk+8)*BST + bn+3] = f2tf32(pb1.w);
    }
    __syncthreads();

    for (int t=0; t<nt; t++){
        int cur = t & 1;
        if (t+1 < nt){
            const float* ag = Ag + (t+1)*16;
            const float* bg = Bg + (long)(t+1)*16*ldb;
            pa0 = *(const float4*)(ag);
            pa1 = *(const float4*)(ag + 64*(long)lda);
            pb0 = bok ? *(const float4*)(bg)               : make_float4(0,0,0,0);
            pb1 = bok ? *(const float4*)(bg + 8*(long)ldb) : make_float4(0,0,0,0);
        }
        const float* as = As[cur];
        const float* bs = Bs[cur];
        #pragma unroll
        for (int ks=0; ks<2; ks++){
            uint32_t af[4][4], bf[4][2];
            #pragma unroll
            for (int i=0;i<4;i++){
                int rbase = (wm + i*16 + qr)*AST + ks*8 + qc;
                af[i][0] = __float_as_uint(as[rbase]);
                af[i][1] = __float_as_uint(as[rbase + 8*AST]);
                af[i][2] = __float_as_uint(as[rbase + 4]);
                af[i][3] = __float_as_uint(as[rbase + 8*AST + 4]);
            }
            #pragma unroll
            for (int j=0;j<4;j++){
                int cb = wn + j*8 + qr;
                bf[j][0] = __float_as_uint(bs[(ks*8 + qc)*BST + cb]);
                bf[j][1] = __float_as_uint(bs[(ks*8 + qc + 4)*BST + cb]);
            }
            #pragma unroll
            for (int i=0;i<4;i++)
                #pragma unroll
                for (int j=0;j<4;j++){
                    asm volatile(
                        "mma.sync.aligned.m16n8k8.row.col.f32.tf32.tf32.f32 "
                        "{%0,%1,%2,%3},{%4,%5,%6,%7},{%8,%9},{%0,%1,%2,%3};"
                        : "+f"(acc[i][j][0]), "+f"(acc[i][j][1]),
                          "+f"(acc[i][j][2]), "+f"(acc[i][j][3])
                        : "r"(af[i][0]), "r"(af[i][1]), "r"(af[i][2]), "r"(af[i][3]),
                          "r"(bf[j][0]), "r"(bf[j][1]));
                }
        }
        if (t+1 < nt){
            float* asw = As[1-cur]; float* bsw = Bs[1-cur];
            asw[ar*AST + ac+0] = f2tf32(pa0.x); asw[ar*AST + ac+1] = f2tf32(pa0.y);
            asw[ar*AST + ac+2] = f2tf32(pa0.z); asw[ar*AST + ac+3] = f2tf32(pa0.w);
            asw[(ar+64)*AST + ac+0] = f2tf32(pa1.x); asw[(ar+64)*AST + ac+1] = f2tf32(pa1.y);
            asw[(ar+64)*AST + ac+2] = f2tf32(pa1.z); asw[(ar+64)*AST + ac+3] = f2tf32(pa1.w);
            bsw[bk*BST + bn+0] = f2tf32(pb0.x); bsw[bk*BST + bn+1] = f2tf32(pb0.y);
            bsw[bk*BST + bn+2] = f2tf32(pb0.z); bsw[bk*BST + bn+3] = f2tf32(pb0.w);
            bsw[(bk+8)*BST + bn+0] = f2tf32(pb1.x); bsw[(bk+8)*BST + bn+1] = f2tf32(pb1.y);
            bsw[(bk+8)*BST + bn+2] = f2tf32(pb1.z); bsw[(bk+8)*BST + bn+3] = f2tf32(pb1.w);
        }
        __syncthreads();
    }

    // epilogue: c0:(qr, 2qc) c1:(qr, 2qc+1) c2:(qr+8, 2qc) c3:(qr+8, 2qc+1)
    #pragma unroll
    for (int i=0;i<4;i++){
        int r0 = row0 + wm + i*16 + qr;
        #pragma unroll
        for (int j=0;j<4;j++){
            int cN = col0 + wn + j*8 + qc*2;
            if (cN < N){
                float bv0 = BIAS ? bias[cN]   : 0.f;
                float bv1 = BIAS ? bias[cN+1] : 0.f;
                long o00 = (long)r0*ldc + cN;
                long o10 = (long)(r0+8)*ldc + cN;
                float v0 = acc[i][j][0] + bv0;
                float v1 = acc[i][j][1] + bv1;
                float v2 = acc[i][j][2] + bv0;
                float v3 = acc[i][j][3] + bv1;
                if (ACC){ v0 += C[o00]; v1 += C[o00+1]; v2 += C[o10]; v3 += C[o10+1]; }
                C[o00]   = v0;
                C[o00+1] = v1;
                C[o10]   = v2;
                C[o10+1] = v3;
            }
        }
    }
}

// ---------------- host ----------------
extern "C" void kernel_launch(void* const* d_in, const int* in_sizes, int n_in,
                              void* d_out, int out_size)
{
    const float* x          = (const float*)d_in[0];
    const float* norm1_w    = (const float*)d_in[1];
    const float* norm2_w    = (const float*)d_in[2];
    const float* norm3_w    = (const float*)d_in[3];
    const float* cs_w       = (const float*)d_in[4];
    const float* cs_b       = (const float*)d_in[5];
    const float* cs_proj_w  = (const float*)d_in[6];
    const float* cs_proj_b  = (const float*)d_in[7];
    const float* gate_proj_w= (const float*)d_in[8];
    const float* router_w   = (const float*)d_in[9];
    const float* router_b   = (const float*)d_in[10];
    const float* head_w     = (const float*)d_in[11];
    const float* head_b     = (const float*)d_in[12];
    const float* mem_q      = (const float*)d_in[13];
    const float* mem_k      = (const float*)d_in[14];
    const float* mem_v      = (const float*)d_in[15];
    const float* mem_gw     = (const float*)d_in[16];
    const float* mem_gb     = (const float*)d_in[17];
    const float* mem_out    = (const float*)d_in[18];
    const float* mixgate_w  = (const float*)d_in[19];
    const float* mixgate_b  = (const float*)d_in[20];
    const float* mixing_w   = (const float*)d_in[21];
    const float* mixing_b   = (const float*)d_in[22];
    const float* ffn_in_w   = (const float*)d_in[23];
    const float* ffn_out_w  = (const float*)d_in[24];
    const float* cg_w       = (const float*)d_in[25];
    const float* cg_b       = (const float*)d_in[26];
    const float* sg_w       = (const float*)d_in[27];
    const float* sg_b       = (const float*)d_in[28];
    const float* fg_w       = (const float*)d_in[29];
    const float* fg_b       = (const float*)d_in[30];

    float *X,*A,*Bb,*C,*D,*GP,*FFN,*GLU,*Q,*Kb,*V,*R,*G,*GA,*GATE,*HW;
    cudaGetSymbolAddress((void**)&X,  g_x);
    cudaGetSymbolAddress((void**)&A,  g_a);
    cudaGetSymbolAddress((void**)&Bb, g_b);
    cudaGetSymbolAddress((void**)&C,  g_c);
    cudaGetSymbolAddress((void**)&D,  g_d);
    cudaGetSymbolAddress((void**)&GP, g_gp);
    cudaGetSymbolAddress((void**)&FFN,g_ffn);
    cudaGetSymbolAddress((void**)&GLU,g_glu);
    cudaGetSymbolAddress((void**)&Q,  g_q);
    cudaGetSymbolAddress((void**)&Kb, g_k);
    cudaGetSymbolAddress((void**)&V,  g_v);
    cudaGetSymbolAddress((void**)&R,  g_r);
    cudaGetSymbolAddress((void**)&G,  g_g);
    cudaGetSymbolAddress((void**)&GA, g_ga);
    cudaGetSymbolAddress((void**)&GATE,g_gate);
    cudaGetSymbolAddress((void**)&HW, g_hw);

    cudaFuncSetAttribute(scan_kernel, cudaFuncAttributeMaxDynamicSharedMemorySize, 69632);

    const int EB = 36864; // TOTAL/256

    // ===== stage 1: conv stack =====
    rms_gate_kernel<<<NTOK,256>>>(x, norm1_w, cg_w, cg_b, A, GATE);
    {
        const int dil[6] = {1,2,4,8,16,32};
        float* pin = A; float* pout = Bb;
        for (int i=0;i<6;i++){
            conv_cs_kernel<<<EB,256>>>(pin, pout, cs_w + i*HDIM*4, cs_b + i*HDIM, dil[i]);
            float* tmp = pin; pin = pout; pout = tmp;
        }
    }
    tgemm<true,false><<<dim3(9,64,1),256>>>(A, cs_proj_w, cs_proj_b, C,
        NTOK, HDIM, HDIM, HDIM, HDIM, HDIM, 0,0,0);
    resid_kernel<<<EB,256>>>(x, C, GATE, X);

    // ===== stage 2: multi-head state =====
    rms_gate_kernel<<<NTOK,256>>>(X, norm2_w, sg_w, sg_b, A, GATE);
    sgemm<true,false,1><<<dim3(1,64,1),256>>>(A, router_w, router_b, HW,
        NTOK, 12, HDIM, HDIM, 12, 12, 0,0,0);
    tgemm<false,false><<<dim3(18,64,1),256>>>(A, gate_proj_w, nullptr, GP,
        NTOK, 2304, HDIM, HDIM, 2304, 2304, 0,0,0);
    glu_kernel<<<EB,256>>>(GP, Bb, HDIM, TOTAL);
    memg_kernel<<<NTOK,128>>>(Bb, mem_gw, mem_gb, G);
    ga_kernel<<<2,256>>>(G, GA);
    tgemm<false,false><<<dim3(1,64,4),256>>>(Bb + 6*HDH, mem_q, nullptr, Q,
        NTOK, HDH, HDH, HDIM, HDH, NMH*HDH, HDH, HDH*HDH, HDH);
    tgemm<false,false><<<dim3(1,64,4),256>>>(Bb + 6*HDH, mem_k, nullptr, Kb,
        NTOK, HDH, HDH, HDIM, HDH, NMH*HDH, HDH, HDH*HDH, HDH);
    tgemm<false,false><<<dim3(1,64,4),256>>>(Bb + 6*HDH, mem_v, nullptr, V,
        NTOK, MDH, HDH, HDIM, MDH, NMH*MDH, HDH, HDH*MDH, MDH);
    conv_head_kernel<<<EB,256>>>(Bb, C, head_w, head_b, 0);
    conv_head_kernel<<<EB,256>>>(C,  A, head_w, head_b, 1);
    conv_head_kernel<<<EB,256>>>(A,  C, head_w, head_b, 2);
    scan_kernel<<<dim3(16,4),256,69632>>>(Q, Kb, V, G, GA, R);
    tgemm<false,true><<<dim3(1,64,4),256>>>(R, mem_out, nullptr, C + 6*HDH,
        NTOK, HDH, MDH, NMH*MDH, HDH, HDIM, MDH, MDH*HDH, HDH);
    hwmul_kernel<<<EB,256>>>(C, HW);
    tgemm<true,false><<<dim3(9,64,1),256>>>(C, mixgate_w, mixgate_b, D,
        NTOK, HDIM, HDIM, HDIM, HDIM, HDIM, 0,0,0);
    mulsig_kernel<<<EB,256>>>(C, D);
    tgemm<true,false><<<dim3(9,64,1),256>>>(C, mixing_w, mixing_b, D,
        NTOK, HDIM, HDIM, HDIM, HDIM, HDIM, 0,0,0);
    resid_kernel<<<EB,256>>>(X, D, GATE, X);

    // ===== stage 3: GLU FFN =====
    rms_gate_kernel<<<NTOK,256>>>(X, norm3_w, fg_w, fg_b, A, GATE);
    tgemm<false,false><<<dim3(72,64,1),256>>>(A, ffn_in_w, nullptr, FFN,
        NTOK, 9216, HDIM, HDIM, 9216, 9216, 0,0,0);
    glu_kernel<<<(NTOK*INNERD+255)/256,256>>>(FFN, GLU, INNERD, NTOK*INNERD);
    tgemm<false,false><<<dim3(9,64,1),256>>>(GLU, ffn_out_w, nullptr, C,
        NTOK, HDIM, INNERD, INNERD, HDIM, HDIM, 0,0,0);
    resid_kernel<<<EB,256>>>(X, C, GATE, (float*)d_out);

    (void)in_sizes; (void)n_in; (void)out_size;
}

// round 6
// speedup vs baseline: 2.2136x; 1.0141x over previous
#include <cuda_runtime.h>
#include <math.h>
#include <stdint.h>

#define NTOK  8192      // B*S
#define HDIM  1152
#define TOTAL (NTOK*HDIM)
#define SEQ   2048
#define INNERD 4608
#define NMH   4
#define HDH   96
#define MDH   128

// ---------------- scratch (device globals; no allocs allowed) ----------------
__device__ float g_x  [TOTAL];
__device__ float g_a  [TOTAL];
__device__ float g_b  [TOTAL];
__device__ float g_c  [TOTAL];
__device__ float g_d  [TOTAL];
__device__ float g_gp [NTOK*2304];
__device__ float g_ffn[NTOK*9216];
__device__ float g_glu[NTOK*INNERD];
__device__ float g_q  [NTOK*NMH*HDH];
__device__ float g_k  [NTOK*NMH*HDH];
__device__ float g_v  [NTOK*NMH*MDH];
__device__ float g_r  [NTOK*NMH*MDH];
__device__ float g_g  [NTOK*NMH];
__device__ float g_ga [4*32*NMH];
__device__ float g_gate[NTOK];
__device__ float g_hw [NTOK*12];

__constant__ int c_head_dil[12][3] = {
  {1,2,4},{1,1,1},{4,8,16},{8,16,32},{32,64,128},{64,128,256},
  {256,512,1024},{1,100,200},{1,500,1000},{1,1024,2048},{3,9,27},{5,25,125}
};

__device__ __forceinline__ float sigmoidf_(float x){ return 1.f/(1.f+__expf(-x)); }
__device__ __forceinline__ float f2tf32(float f){
    uint32_t r; asm("cvt.rna.tf32.f32 %0,%1;" : "=r"(r) : "f"(f));
    return __uint_as_float(r);
}

// ---------------- fused rmsnorm + token scalar gate ----------------
__global__ void rms_gate_kernel(const float* __restrict__ x, const float* __restrict__ nw,
                                const float* __restrict__ gw, const float* __restrict__ gb,
                                float* __restrict__ xn, float* __restrict__ gate)
{
    __shared__ float s1[8], s2[8], sinv;
    int t = blockIdx.x;
    const float* xr = x + (long)t*HDIM;
    float ss=0.f, dg=0.f;
    for (int c=threadIdx.x; c<HDIM; c+=256){ float v=xr[c]; ss+=v*v; dg+=v*gw[c]; }
    for (int o=16;o;o>>=1){ ss+=__shfl_down_sync(~0u,ss,o); dg+=__shfl_down_sync(~0u,dg,o); }
    int w=threadIdx.x>>5, l=threadIdx.x&31;
    if (l==0){ s1[w]=ss; s2[w]=dg; }
    __syncthreads();
    if (threadIdx.x==0){
        float a=0,bq=0;
        #pragma unroll
        for (int i=0;i<8;i++){ a+=s1[i]; bq+=s2[i]; }
        sinv = rsqrtf(a/(float)HDIM + 1e-6f);
        gate[t] = 1.f/(1.f+expf(-(bq+gb[0])));
    }
    __syncthreads();
    float inv = sinv;
    for (int c=threadIdx.x; c<HDIM; c+=256) xn[(long)t*HDIM+c] = xr[c]*inv*nw[c];
}

// ---------------- conv stack layer ----------------
__global__ void conv_cs_kernel(const float* __restrict__ in, float* __restrict__ out,
                               const float* __restrict__ w, const float* __restrict__ bias, int d)
{
    int idx = blockIdx.x*256 + threadIdx.x;
    if (idx >= TOTAL) return;
    int c = idx % HDIM;
    int t = idx / HDIM;
    int s = t & (SEQ-1);
    float acc = bias[c];
    const float* wc = w + c*4;
    #pragma unroll
    for (int j=0;j<4;j++){
        int sp = s - (3-j)*d;
        if (sp >= 0) acc += wc[j] * in[idx + (sp - s)*HDIM];
    }
    float g = 0.5f*acc*(1.f + erff(acc*0.70710678118654752f));
    out[idx] = in[idx] + g;
}

// ---------------- head conv layer ----------------
__global__ void conv_head_kernel(const float* __restrict__ in, float* __restrict__ out,
                                 const float* __restrict__ hw, const float* __restrict__ hb, int layer)
{
    int idx = blockIdx.x*256 + threadIdx.x;
    if (idx >= TOTAL) return;
    int ch = idx % HDIM;
    int i  = ch / HDH;
    int c  = ch % HDH;
    int t  = idx / HDIM;
    int s  = t & (SEQ-1);
    int d  = c_head_dil[i][layer];
    int wb = (i*3 + layer)*HDH + c;
    const float* wc = hw + wb*4;
    float acc = hb[wb];
    #pragma unroll
    for (int j=0;j<4;j++){
        int sp = s - (3-j)*d;
        if (sp >= 0) acc += wc[j] * in[idx + (sp - s)*HDIM];
    }
    out[idx] = in[idx] + acc;
}

// ---------------- elementwise ----------------
__global__ void glu_kernel(const float* __restrict__ in, float* __restrict__ out, int half, int total)
{
    int idx = blockIdx.x*256 + threadIdx.x;
    if (idx >= total) return;
    int t = idx / half, c = idx % half;
    float a = in[t*2*half + c];
    float bq = in[t*2*half + half + c];
    out[idx] = a * sigmoidf_(bq);
}

__global__ void hwmul_kernel(float* __restrict__ a, const float* __restrict__ hw)
{
    int idx = blockIdx.x*256 + threadIdx.x;
    if (idx >= TOTAL) return;
    int t = idx / HDIM, h = (idx % HDIM)/HDH;
    a[idx] *= hw[t*12 + h];
}

// ---------------- memory-head gate g and chunk means ----------------
__global__ void memg_kernel(const float* __restrict__ xg, const float* __restrict__ gw,
                            const float* __restrict__ gb, float* __restrict__ g)
{
    int t = blockIdx.x;
    int warp = threadIdx.x >> 5, lane = threadIdx.x & 31;
    const float* xr = xg + (long)t*HDIM + (6+warp)*HDH;
    const float* w  = gw + warp*HDH;
    float acc = 0.f;
    for (int c=lane;c<HDH;c+=32) acc += xr[c]*w[c];
    for (int o=16;o;o>>=1) acc += __shfl_down_sync(~0u,acc,o);
    if (lane==0) g[t*NMH+warp] = 1.f/(1.f+expf(-(acc + gb[warp])));
}

__global__ void ga_kernel(const float* __restrict__ g, float* __restrict__ ga)
{
    int e = blockIdx.x*256 + threadIdx.x;
    if (e >= 4*32*NMH) return;
    int n = e % NMH, ch = (e/NMH) % 32, b = e/(NMH*32);
    int base = (b*SEQ + ch*64)*NMH + n;
    float s = 0.f;
    for (int i=0;i<64;i++) s += g[base + i*NMH];
    ga[e] = s*(1.f/64.f);
}

// ---------------- chunked fast-weight scan ----------------
__global__ void scan_kernel(const float* __restrict__ q, const float* __restrict__ kk,
                            const float* __restrict__ v, const float* __restrict__ g,
                            const float* __restrict__ ga, float* __restrict__ reads)
{
    extern __shared__ float smx[];
    float* sM = smx;             // 96*32
    float* sQ = sM + 96*32;      // 64*96
    float* sK = sQ + 64*96;      // 64*96
    float* sV = sK + 64*96;      // 64*32
    int bn = blockIdx.x;
    int b = bn >> 2, n = bn & 3;
    int m0 = blockIdx.y * 32;
    int tid = threadIdx.x;
    for (int i=tid;i<96*32;i+=256) sM[i]=0.f;
    __syncthreads();
    for (int ch=0; ch<32; ch++){
        int tok0 = b*SEQ + ch*64;
        for (int i=tid;i<64*96;i+=256){
            int s = i/96, dd = i%96;
            int gi = (tok0+s)*(NMH*HDH) + n*HDH + dd;
            sQ[i] = q[gi];
            sK[i] = kk[gi] * g[(tok0+s)*NMH + n];
        }
        for (int i=tid;i<64*32;i+=256){
            int s=i/32, m=i%32;
            sV[i] = v[(tok0+s)*(NMH*MDH) + n*MDH + m0 + m];
        }
        __syncthreads();
        for (int o=tid;o<64*32;o+=256){
            int s=o/32, m=o%32;
            float acc=0.f;
            const float* qs = sQ + s*96;
            #pragma unroll 8
            for (int dd=0; dd<96; dd++) acc += qs[dd]*sM[dd*32+m];
            reads[(tok0+s)*(NMH*MDH) + n*MDH + m0 + m] = acc;
        }
        __syncthreads();
        float gav = ga[(b*32+ch)*NMH + n];
        for (int e=tid;e<96*32;e+=256){
            int dd=e/32, m=e%32;
            float acc = (1.f-gav)*sM[e];
            #pragma unroll 8
            for (int s=0;s<64;s++) acc += sK[s*96+dd]*sV[s*32+m];
            sM[e]=acc;
        }
        __syncthreads();
    }
}

// ---------------- SIMT fp32 GEMM (router, N=12) ----------------
template<bool BIAS, bool ACC, int ACT>
__global__ __launch_bounds__(256) void sgemm(
    const float* __restrict__ A, const float* __restrict__ B,
    const float* __restrict__ bias, float* __restrict__ C,
    int M, int N, int K, int lda, int ldb, int ldc,
    long sA, long sB, long sC)
{
    __shared__ __align__(16) float As[8*128];
    __shared__ __align__(16) float Bs[8*128];
    A += (long)blockIdx.z * sA;
    B += (long)blockIdx.z * sB;
    C += (long)blockIdx.z * sC;
    int tid = threadIdx.x;
    int row0 = blockIdx.y * 128;
    int col0 = blockIdx.x * 128;
    int tr4 = (tid >> 4) * 4;
    int tc4 = (tid & 15) * 4;
    int arow = tid >> 1, acol = (tid & 1) * 4;
    int brow = tid >> 5, bcol = (tid & 31) * 4;
    const float* Aptr = A + (long)(row0 + arow)*lda + acol;
    const float* Bptr = B + (long)brow*ldb + col0 + bcol;
    bool bvalid = (col0 + bcol + 3) < N;
    float acc[8][8];
    #pragma unroll
    for (int i=0;i<8;i++)
        #pragma unroll
        for (int j=0;j<8;j++) acc[i][j]=0.f;

    for (int k0=0;k0<K;k0+=8){
        float4 av = *(const float4*)Aptr;
        As[(acol+0)*128 + arow]=av.x;
        As[(acol+1)*128 + arow]=av.y;
        As[(acol+2)*128 + arow]=av.z;
        As[(acol+3)*128 + arow]=av.w;
        float4 bv = bvalid ? *(const float4*)Bptr : make_float4(0.f,0.f,0.f,0.f);
        *(float4*)&Bs[brow*128 + bcol] = bv;
        __syncthreads();
        #pragma unroll
        for (int k=0;k<8;k++){
            float4 a0 = *(const float4*)&As[k*128 + tr4];
            float4 a1 = *(const float4*)&As[k*128 + tr4 + 64];
            float4 b0 = *(const float4*)&Bs[k*128 + tc4];
            float4 b1 = *(const float4*)&Bs[k*128 + tc4 + 64];
            float ra[8] = {a0.x,a0.y,a0.z,a0.w,a1.x,a1.y,a1.z,a1.w};
            float rb[8] = {b0.x,b0.y,b0.z,b0.w,b1.x,b1.y,b1.z,b1.w};
            #pragma unroll
            for (int i=0;i<8;i++)
                #pragma unroll
                for (int j=0;j<8;j++) acc[i][j] += ra[i]*rb[j];
        }
        __syncthreads();
        Aptr += 8;
        Bptr += 8*(long)ldb;
    }
    #pragma unroll
    for (int i=0;i<8;i++){
        int r = row0 + tr4 + (i<4 ? i : i-4+64);
        #pragma unroll
        for (int j=0;j<8;j++){
            int cN = col0 + tc4 + (j<4 ? j : j-4+64);
            if (cN < N){
                float v = acc[i][j];
                if (BIAS) v += bias[cN];
                if (ACC)  v += C[(long)r*ldc + cN];
                if (ACT==1) v = 1.f/(1.f+expf(-v));
                C[(long)r*ldc + cN] = v;
            }
        }
    }
}

// ---------------- tf32 tensor-core GEMM (round-2 proven core) ----------------
// C = EPIfn(A@B [+bias]). B is the ORIGINAL [K][N] layout.
// EPI: 0 plain, 1 resid C=E+gate[r]*(acc+bias), 2 mulsig C=E*sig(acc+bias), 3 C+=acc
// 128x128x16 tiles, 256 threads = 8 warps (2Mx4N), warp tile 64x32.
#define AST 20
#define BST 136
template<bool BIAS, int EPI>
__global__ __launch_bounds__(256) void tgemm(
    const float* __restrict__ A, const float* __restrict__ B,
    const float* __restrict__ bias, float* __restrict__ C,
    const float* __restrict__ E, const float* __restrict__ gate,
    int M, int N, int K, int lda, int ldb, int ldc,
    long sA, long sB, long sC)
{
    __shared__ __align__(16) float As[2][128*AST];
    __shared__ __align__(16) float Bs[2][16*BST];

    A += (long)blockIdx.z * sA;
    B += (long)blockIdx.z * sB;
    C += (long)blockIdx.z * sC;
    if (EPI == 1 || EPI == 2) E += (long)blockIdx.z * sC;

    const int tid  = threadIdx.x;
    const int lane = tid & 31;
    const int wid  = tid >> 5;
    const int wm   = (wid >> 2) * 64;
    const int wn   = (wid & 3) * 32;
    const int qr   = lane >> 2;
    const int qc   = lane & 3;

    const int row0 = blockIdx.y * 128;
    const int col0 = blockIdx.x * 128;

    const int ar = tid >> 2;
    const int ac = (tid & 3) * 4;
    const int bk = tid >> 5;
    const int bn = lane * 4;
    const bool bok = (col0 + bn + 3) < N;

    const float* Ag = A + (long)(row0 + ar)*lda + ac;
    const float* Bg = B + (long)bk*ldb + col0 + bn;

    float acc[4][4][4];
    #pragma unroll
    for (int i=0;i<4;i++)
        #pragma unroll
        for (int j=0;j<4;j++)
            #pragma unroll
            for (int e=0;e<4;e++) acc[i][j][e]=0.f;

    const int nt = K >> 4;
    float4 pa0, pa1, pb0, pb1;

    pa0 = *(const float4*)(Ag);
    pa1 = *(const float4*)(Ag + 64*(long)lda);
    pb0 = bok ? *(const float4*)(Bg)               : make_float4(0,0,0,0);
    pb1 = bok ? *(const float4*)(Bg + 8*(long)ldb) : make_float4(0,0,0,0);
    {
        float* as = As[0]; float* bs = Bs[0];
        as[ar*AST + ac+0] = f2tf32(pa0.x); as[ar*AST + ac+1] = f2tf32(pa0.y);
        as[ar*AST + ac+2] = f2tf32(pa0.z); as[ar*AST + ac+3] = f2tf32(pa0.w);
        as[(ar+64)*AST + ac+0] = f2tf32(pa1.x); as[(ar+64)*AST + ac+1] = f2tf32(pa1.y);
        as[(ar+64)*AST + ac+2] = f2tf32(pa1.z); as[(ar+64)*AST + ac+3] = f2tf32(pa1.w);
        bs[bk*BST + bn+0] = f2tf32(pb0.x); bs[bk*BST + bn+1] = f2tf32(pb0.y);
        bs[bk*BST + bn+2] = f2tf32(pb0.z); bs[bk*BST + bn+3] = f2tf32(pb0.w);
        bs[(bk+8)*BST + bn+0] = f2tf32(pb1.x); bs[(bk+8)*BST + bn+1] = f2tf32(pb1.y);
        bs[(bk+8)*BST + bn+2] = f2tf32(pb1.z); bs[(bk+8)*BST + bn+3] = f2tf32(pb1.w);
    }
    __syncthreads();

    for (int t=0; t<nt; t++){
        int cur = t & 1;
        if (t+1 < nt){
            const float* ag = Ag + (t+1)*16;
            const float* bg = Bg + (long)(t+1)*16*ldb;
            pa0 = *(const float4*)(ag);
            pa1 = *(const float4*)(ag + 64*(long)lda);
            pb0 = bok ? *(const float4*)(bg)               : make_float4(0,0,0,0);
            pb1 = bok ? *(const float4*)(bg + 8*(long)ldb) : make_float4(0,0,0,0);
        }
        const float* as = As[cur];
        const float* bs = Bs[cur];
        #pragma unroll
        for (int ks=0; ks<2; ks++){
            uint32_t af[4][4], bf[4][2];
            #pragma unroll
            for (int i=0;i<4;i++){
                int rbase = (wm + i*16 + qr)*AST + ks*8 + qc;
                af[i][0] = __float_as_uint(as[rbase]);
                af[i][1] = __float_as_uint(as[rbase + 8*AST]);
                af[i][2] = __float_as_uint(as[rbase + 4]);
                af[i][3] = __float_as_uint(as[rbase + 8*AST + 4]);
            }
            #pragma unroll
            for (int j=0;j<4;j++){
                int cb = wn + j*8 + qr;
                bf[j][0] = __float_as_uint(bs[(ks*8 + qc)*BST + cb]);
                bf[j][1] = __float_as_uint(bs[(ks*8 + qc + 4)*BST + cb]);
            }
            #pragma unroll
            for (int i=0;i<4;i++)
                #pragma unroll
                for (int j=0;j<4;j++){
                    asm volatile(
                        "mma.sync.aligned.m16n8k8.row.col.f32.tf32.tf32.f32 "
                        "{%0,%1,%2,%3},{%4,%5,%6,%7},{%8,%9},{%0,%1,%2,%3};"
                        : "+f"(acc[i][j][0]), "+f"(acc[i][j][1]),
                          "+f"(acc[i][j][2]), "+f"(acc[i][j][3])
                        : "r"(af[i][0]), "r"(af[i][1]), "r"(af[i][2]), "r"(af[i][3]),
                          "r"(bf[j][0]), "r"(bf[j][1]));
                }
        }
        if (t+1 < nt){
            float* asw = As[1-cur]; float* bsw = Bs[1-cur];
            asw[ar*AST + ac+0] = f2tf32(pa0.x); asw[ar*AST + ac+1] = f2tf32(pa0.y);
            asw[ar*AST + ac+2] = f2tf32(pa0.z); asw[ar*AST + ac+3] = f2tf32(pa0.w);
            asw[(ar+64)*AST + ac+0] = f2tf32(pa1.x); asw[(ar+64)*AST + ac+1] = f2tf32(pa1.y);
            asw[(ar+64)*AST + ac+2] = f2tf32(pa1.z); asw[(ar+64)*AST + ac+3] = f2tf32(pa1.w);
            bsw[bk*BST + bn+0] = f2tf32(pb0.x); bsw[bk*BST + bn+1] = f2tf32(pb0.y);
            bsw[bk*BST + bn+2] = f2tf32(pb0.z); bsw[bk*BST + bn+3] = f2tf32(pb0.w);
            bsw[(bk+8)*BST + bn+0] = f2tf32(pb1.x); bsw[(bk+8)*BST + bn+1] = f2tf32(pb1.y);
            bsw[(bk+8)*BST + bn+2] = f2tf32(pb1.z); bsw[(bk+8)*BST + bn+3] = f2tf32(pb1.w);
        }
        __syncthreads();
    }

    // epilogue
    #pragma unroll
    for (int i=0;i<4;i++){
        int r0 = row0 + wm + i*16 + qr;
        float gg0 = 0.f, gg1 = 0.f;
        if (EPI == 1){ gg0 = gate[r0]; gg1 = gate[r0+8]; }
        #pragma unroll
        for (int j=0;j<4;j++){
            int cN = col0 + wn + j*8 + qc*2;
            if (cN < N){
                float bv0 = BIAS ? bias[cN]   : 0.f;
                float bv1 = BIAS ? bias[cN+1] : 0.f;
                long o00 = (long)r0*ldc + cN;
                long o10 = (long)(r0+8)*ldc + cN;
                float v0 = acc[i][j][0] + bv0;
                float v1 = acc[i][j][1] + bv1;
                float v2 = acc[i][j][2] + bv0;
                float v3 = acc[i][j][3] + bv1;
                if (EPI == 1){
                    v0 = E[o00]   + gg0*v0;
                    v1 = E[o00+1] + gg0*v1;
                    v2 = E[o10]   + gg1*v2;
                    v3 = E[o10+1] + gg1*v3;
                } else if (EPI == 2){
                    v0 = E[o00]  *sigmoidf_(v0);
                    v1 = E[o00+1]*sigmoidf_(v1);
                    v2 = E[o10]  *sigmoidf_(v2);
                    v3 = E[o10+1]*sigmoidf_(v3);
                } else if (EPI == 3){
                    v0 += C[o00]; v1 += C[o00+1]; v2 += C[o10]; v3 += C[o10+1];
                }
                C[o00]   = v0;
                C[o00+1] = v1;
                C[o10]   = v2;
                C[o10+1] = v3;
            }
        }
    }
}

// ---------------- host ----------------
extern "C" void kernel_launch(void* const* d_in, const int* in_sizes, int n_in,
                              void* d_out, int out_size)
{
    const float* x          = (const float*)d_in[0];
    const float* norm1_w    = (const float*)d_in[1];
    const float* norm2_w    = (const float*)d_in[2];
    const float* norm3_w    = (const float*)d_in[3];
    const float* cs_w       = (const float*)d_in[4];
    const float* cs_b       = (const float*)d_in[5];
    const float* cs_proj_w  = (const float*)d_in[6];
    const float* cs_proj_b  = (const float*)d_in[7];
    const float* gate_proj_w= (const float*)d_in[8];
    const float* router_w   = (const float*)d_in[9];
    const float* router_b   = (const float*)d_in[10];
    const float* head_w     = (const float*)d_in[11];
    const float* head_b     = (const float*)d_in[12];
    const float* mem_q      = (const float*)d_in[13];
    const float* mem_k      = (const float*)d_in[14];
    const float* mem_v      = (const float*)d_in[15];
    const float* mem_gw     = (const float*)d_in[16];
    const float* mem_gb     = (const float*)d_in[17];
    const float* mem_out    = (const float*)d_in[18];
    const float* mixgate_w  = (const float*)d_in[19];
    const float* mixgate_b  = (const float*)d_in[20];
    const float* mixing_w   = (const float*)d_in[21];
    const float* mixing_b   = (const float*)d_in[22];
    const float* ffn_in_w   = (const float*)d_in[23];
    const float* ffn_out_w  = (const float*)d_in[24];
    const float* cg_w       = (const float*)d_in[25];
    const float* cg_b       = (const float*)d_in[26];
    const float* sg_w       = (const float*)d_in[27];
    const float* sg_b       = (const float*)d_in[28];
    const float* fg_w       = (const float*)d_in[29];
    const float* fg_b       = (const float*)d_in[30];

    float *X,*A,*Bb,*C,*D,*GP,*FFN,*GLU,*Q,*Kb,*V,*R,*G,*GA,*GATE,*HW;
    cudaGetSymbolAddress((void**)&X,  g_x);
    cudaGetSymbolAddress((void**)&A,  g_a);
    cudaGetSymbolAddress((void**)&Bb, g_b);
    cudaGetSymbolAddress((void**)&C,  g_c);
    cudaGetSymbolAddress((void**)&D,  g_d);
    cudaGetSymbolAddress((void**)&GP, g_gp);
    cudaGetSymbolAddress((void**)&FFN,g_ffn);
    cudaGetSymbolAddress((void**)&GLU,g_glu);
    cudaGetSymbolAddress((void**)&Q,  g_q);
    cudaGetSymbolAddress((void**)&Kb, g_k);
    cudaGetSymbolAddress((void**)&V,  g_v);
    cudaGetSymbolAddress((void**)&R,  g_r);
    cudaGetSymbolAddress((void**)&G,  g_g);
    cudaGetSymbolAddress((void**)&GA, g_ga);
    cudaGetSymbolAddress((void**)&GATE,g_gate);
    cudaGetSymbolAddress((void**)&HW, g_hw);

    cudaFuncSetAttribute(scan_kernel, cudaFuncAttributeMaxDynamicSharedMemorySize, 69632);

    const int EB = 36864; // TOTAL/256

    // ===== stage 1: conv stack =====
    rms_gate_kernel<<<NTOK,256>>>(x, norm1_w, cg_w, cg_b, A, GATE);
    {
        const int dil[6] = {1,2,4,8,16,32};
        float* pin = A; float* pout = Bb;
        for (int i=0;i<6;i++){
            conv_cs_kernel<<<EB,256>>>(pin, pout, cs_w + i*HDIM*4, cs_b + i*HDIM, dil[i]);
            float* tmp = pin; pin = pout; pout = tmp;
        }
    }
    // X = x + gate*(A@cs_proj + b)
    tgemm<true,1><<<dim3(9,64,1),256>>>(A, cs_proj_w, cs_proj_b, X, x, GATE,
        NTOK, HDIM, HDIM, HDIM, HDIM, HDIM, 0,0,0);

    // ===== stage 2: multi-head state =====
    rms_gate_kernel<<<NTOK,256>>>(X, norm2_w, sg_w, sg_b, A, GATE);
    sgemm<true,false,1><<<dim3(1,64,1),256>>>(A, router_w, router_b, HW,
        NTOK, 12, HDIM, HDIM, 12, 12, 0,0,0);
    tgemm<false,0><<<dim3(18,64,1),256>>>(A, gate_proj_w, nullptr, GP, nullptr, nullptr,
        NTOK, 2304, HDIM, HDIM, 2304, 2304, 0,0,0);
    glu_kernel<<<EB,256>>>(GP, Bb, HDIM, TOTAL);
    memg_kernel<<<NTOK,128>>>(Bb, mem_gw, mem_gb, G);
    ga_kernel<<<2,256>>>(G, GA);
    tgemm<false,0><<<dim3(1,64,4),256>>>(Bb + 6*HDH, mem_q, nullptr, Q, nullptr, nullptr,
        NTOK, HDH, HDH, HDIM, HDH, NMH*HDH, HDH, HDH*HDH, HDH);
    tgemm<false,0><<<dim3(1,64,4),256>>>(Bb + 6*HDH, mem_k, nullptr, Kb, nullptr, nullptr,
        NTOK, HDH, HDH, HDIM, HDH, NMH*HDH, HDH, HDH*HDH, HDH);
    tgemm<false,0><<<dim3(1,64,4),256>>>(Bb + 6*HDH, mem_v, nullptr, V, nullptr, nullptr,
        NTOK, MDH, HDH, HDIM, MDH, NMH*MDH, HDH, HDH*MDH, MDH);
    conv_head_kernel<<<EB,256>>>(Bb, C, head_w, head_b, 0);
    conv_head_kernel<<<EB,256>>>(C,  A, head_w, head_b, 1);
    conv_head_kernel<<<EB,256>>>(A,  C, head_w, head_b, 2);
    scan_kernel<<<dim3(16,4),256,69632>>>(Q, Kb, V, G, GA, R);
    // C[:, memheads] += R @ mem_out
    tgemm<false,3><<<dim3(1,64,4),256>>>(R, mem_out, nullptr, C + 6*HDH, nullptr, nullptr,
        NTOK, HDH, MDH, NMH*MDH, HDH, HDIM, MDH, MDH*HDH, HDH);
    hwmul_kernel<<<EB,256>>>(C, HW);
    // D = C * sigmoid(C@mixgate + b)
    tgemm<true,2><<<dim3(9,64,1),256>>>(C, mixgate_w, mixgate_b, D, C, nullptr,
        NTOK, HDIM, HDIM, HDIM, HDIM, HDIM, 0,0,0);
    // X = X + gate*(D@mixing + b)
    tgemm<true,1><<<dim3(9,64,1),256>>>(D, mixing_w, mixing_b, X, X, GATE,
        NTOK, HDIM, HDIM, HDIM, HDIM, HDIM, 0,0,0);

    // ===== stage 3: GLU FFN =====
    rms_gate_kernel<<<NTOK,256>>>(X, norm3_w, fg_w, fg_b, A, GATE);
    tgemm<false,0><<<dim3(72,64,1),256>>>(A, ffn_in_w, nullptr, FFN, nullptr, nullptr,
        NTOK, 9216, HDIM, HDIM, 9216, 9216, 0,0,0);
    glu_kernel<<<(NTOK*INNERD+255)/256,256>>>(FFN, GLU, INNERD, NTOK*INNERD);
    // out = X + gate*(GLU@ffn_out)
    tgemm<false,1><<<dim3(9,64,1),256>>>(GLU, ffn_out_w, nullptr, (float*)d_out, X, GATE,
        NTOK, HDIM, INNERD, INNERD, HDIM, HDIM, 0,0,0);

    (void)in_sizes; (void)n_in; (void)out_size;
}

// round 7
// speedup vs baseline: 2.2664x; 1.0238x over previous
#include <cuda_runtime.h>
#include <math.h>
#include <stdint.h>

#define NTOK  8192      // B*S
#define HDIM  1152
#define TOTAL (NTOK*HDIM)
#define SEQ   2048
#define INNERD 4608
#define NMH   4
#define HDH   96
#define MDH   128
#define H4    (HDIM/4)   // 288

// ---------------- scratch (device globals; no allocs allowed) ----------------
__device__ float g_x  [TOTAL];
__device__ float g_a  [TOTAL];
__device__ float g_b  [TOTAL];
__device__ float g_c  [TOTAL];
__device__ float g_d  [TOTAL];
__device__ float g_glu[NTOK*INNERD];
__device__ float g_q  [NTOK*NMH*HDH];
__device__ float g_k  [NTOK*NMH*HDH];
__device__ float g_v  [NTOK*NMH*MDH];
__device__ float g_r  [NTOK*NMH*MDH];
__device__ float g_g  [NTOK*NMH];
__device__ float g_ga [4*32*NMH];
__device__ float g_gate[NTOK];
__device__ float g_hw [NTOK*12];
// pair-interleaved weights for fused GLU epilogue
__device__ float g_wp_gp [1152*2304];
__device__ float g_wp_fi [1152*9216];

__constant__ int c_head_dil[12][3] = {
  {1,2,4},{1,1,1},{4,8,16},{8,16,32},{32,64,128},{64,128,256},
  {256,512,1024},{1,100,200},{1,500,1000},{1,1024,2048},{3,9,27},{5,25,125}
};

__device__ __forceinline__ float sigmoidf_(float x){ return 1.f/(1.f+__expf(-x)); }
__device__ __forceinline__ float f2tf32(float f){
    uint32_t r; asm("cvt.rna.tf32.f32 %0,%1;" : "=r"(r) : "f"(f));
    return __uint_as_float(r);
}

// ---------------- column pair-interleave: out[k][2m]=in[k][m], out[k][2m+1]=in[k][half+m]
__global__ void permute_pair(const float* __restrict__ in, float* __restrict__ out, long total, int N)
{
    long idx = (long)blockIdx.x*256 + threadIdx.x;
    if (idx >= total) return;
    long k = idx / N;
    int  j = (int)(idx % N);
    int  h = N >> 1;
    out[idx] = in[k*N + ((j & 1) ? h + (j >> 1) : (j >> 1))];
}

// ---------------- fused rmsnorm + token scalar gate (float4) ----------------
__global__ void rms_gate_kernel(const float* __restrict__ x, const float* __restrict__ nw,
                                const float* __restrict__ gw, const float* __restrict__ gb,
                                float* __restrict__ xn, float* __restrict__ gate)
{
    __shared__ float s1[8], s2[8], sinv;
    int t = blockIdx.x;
    const float4* xr = (const float4*)(x + (long)t*HDIM);
    const float4* gw4 = (const float4*)gw;
    const float4* nw4 = (const float4*)nw;
    float4 vbuf[2];
    float ss=0.f, dg=0.f;
    int nit = 0;
    for (int c=threadIdx.x; c<H4; c+=256){
        float4 v = xr[c]; vbuf[nit++] = v;
        float4 w = gw4[c];
        ss += v.x*v.x + v.y*v.y + v.z*v.z + v.w*v.w;
        dg += v.x*w.x + v.y*w.y + v.z*w.z + v.w*w.w;
    }
    for (int o=16;o;o>>=1){ ss+=__shfl_down_sync(~0u,ss,o); dg+=__shfl_down_sync(~0u,dg,o); }
    int w=threadIdx.x>>5, l=threadIdx.x&31;
    if (l==0){ s1[w]=ss; s2[w]=dg; }
    __syncthreads();
    if (threadIdx.x==0){
        float a=0,bq=0;
        #pragma unroll
        for (int i=0;i<8;i++){ a+=s1[i]; bq+=s2[i]; }
        sinv = rsqrtf(a/(float)HDIM + 1e-6f);
        gate[t] = 1.f/(1.f+expf(-(bq+gb[0])));
    }
    __syncthreads();
    float inv = sinv;
    float4* xo = (float4*)(xn + (long)t*HDIM);
    nit = 0;
    for (int c=threadIdx.x; c<H4; c+=256){
        float4 v = vbuf[nit++];
        float4 nwv = nw4[c];
        xo[c] = make_float4(v.x*inv*nwv.x, v.y*inv*nwv.y, v.z*inv*nwv.z, v.w*inv*nwv.w);
    }
}

// ---------------- conv stack layer (float4) ----------------
__global__ void conv_cs_kernel(const float4* __restrict__ in, float4* __restrict__ out,
                               const float4* __restrict__ w4, const float4* __restrict__ bias4, int d)
{
    int idx = blockIdx.x*256 + threadIdx.x;
    if (idx >= TOTAL/4) return;
    int c4 = idx % H4;
    int t  = idx / H4;
    int s  = t & (SEQ-1);
    float4 wv[4];
    #pragma unroll
    for (int u=0;u<4;u++) wv[u] = w4[c4*4 + u];   // channel (4c4+u)'s 4 taps
    const float* wf = (const float*)wv;
    float4 b4 = bias4[c4];
    float acc[4] = {b4.x, b4.y, b4.z, b4.w};
    #pragma unroll
    for (int j=0;j<4;j++){
        int sp = s - (3-j)*d;
        if (sp >= 0){
            float4 xv = in[idx + (sp - s)*H4];
            acc[0] += wf[0*4+j]*xv.x;
            acc[1] += wf[1*4+j]*xv.y;
            acc[2] += wf[2*4+j]*xv.z;
            acc[3] += wf[3*4+j]*xv.w;
        }
    }
    float4 iv = in[idx];
    float4 ov;
    ov.x = iv.x + 0.5f*acc[0]*(1.f + erff(acc[0]*0.70710678118654752f));
    ov.y = iv.y + 0.5f*acc[1]*(1.f + erff(acc[1]*0.70710678118654752f));
    ov.z = iv.z + 0.5f*acc[2]*(1.f + erff(acc[2]*0.70710678118654752f));
    ov.w = iv.w + 0.5f*acc[3]*(1.f + erff(acc[3]*0.70710678118654752f));
    out[idx] = ov;
}

// ---------------- head conv layer (float4) ----------------
__global__ void conv_head_kernel(const float4* __restrict__ in, float4* __restrict__ out,
                                 const float4* __restrict__ hw4, const float* __restrict__ hb, int layer)
{
    int idx = blockIdx.x*256 + threadIdx.x;
    if (idx >= TOTAL/4) return;
    int c4 = idx % H4;
    int t  = idx / H4;
    int s  = t & (SEQ-1);
    int ch = c4*4;
    int head = ch / HDH;
    int cin  = ch % HDH;
    int d = c_head_dil[head][layer];
    int wb = (head*3 + layer)*HDH + cin;    // channel index into (..,96,4)
    float4 wv[4];
    #pragma unroll
    for (int u=0;u<4;u++) wv[u] = hw4[wb + u];
    const float* wf = (const float*)wv;
    float acc[4] = {hb[wb], hb[wb+1], hb[wb+2], hb[wb+3]};
    #pragma unroll
    for (int j=0;j<4;j++){
        int sp = s - (3-j)*d;
        if (sp >= 0){
            float4 xv = in[idx + (sp - s)*H4];
            acc[0] += wf[0*4+j]*xv.x;
            acc[1] += wf[1*4+j]*xv.y;
            acc[2] += wf[2*4+j]*xv.z;
            acc[3] += wf[3*4+j]*xv.w;
        }
    }
    float4 iv = in[idx];
    out[idx] = make_float4(iv.x+acc[0], iv.y+acc[1], iv.z+acc[2], iv.w+acc[3]);
}

// ---------------- hw mul (float4) ----------------
__global__ void hwmul_kernel(float4* __restrict__ a, const float* __restrict__ hw)
{
    int idx = blockIdx.x*256 + threadIdx.x;
    if (idx >= TOTAL/4) return;
    int t = idx / H4, h = (idx % H4)*4/HDH;
    float g = hw[t*12 + h];
    float4 v = a[idx];
    a[idx] = make_float4(v.x*g, v.y*g, v.z*g, v.w*g);
}

// ---------------- memory-head gate g and chunk means ----------------
__global__ void memg_kernel(const float* __restrict__ xg, const float* __restrict__ gw,
                            const float* __restrict__ gb, float* __restrict__ g)
{
    int t = blockIdx.x;
    int warp = threadIdx.x >> 5, lane = threadIdx.x & 31;
    const float* xr = xg + (long)t*HDIM + (6+warp)*HDH;
    const float* w  = gw + warp*HDH;
    float acc = 0.f;
    for (int c=lane;c<HDH;c+=32) acc += xr[c]*w[c];
    for (int o=16;o;o>>=1) acc += __shfl_down_sync(~0u,acc,o);
    if (lane==0) g[t*NMH+warp] = 1.f/(1.f+expf(-(acc + gb[warp])));
}

__global__ void ga_kernel(const float* __restrict__ g, float* __restrict__ ga)
{
    int e = blockIdx.x*256 + threadIdx.x;
    if (e >= 4*32*NMH) return;
    int n = e % NMH, ch = (e/NMH) % 32, b = e/(NMH*32);
    int base = (b*SEQ + ch*64)*NMH + n;
    float s = 0.f;
    for (int i=0;i<64;i++) s += g[base + i*NMH];
    ga[e] = s*(1.f/64.f);
}

// ---------------- chunked fast-weight scan ----------------
__global__ void scan_kernel(const float* __restrict__ q, const float* __restrict__ kk,
                            const float* __restrict__ v, const float* __restrict__ g,
                            const float* __restrict__ ga, float* __restrict__ reads)
{
    extern __shared__ float smx[];
    float* sM = smx;             // 96*32
    float* sQ = sM + 96*32;      // 64*96
    float* sK = sQ + 64*96;      // 64*96
    float* sV = sK + 64*96;      // 64*32
    int bn = blockIdx.x;
    int b = bn >> 2, n = bn & 3;
    int m0 = blockIdx.y * 32;
    int tid = threadIdx.x;
    for (int i=tid;i<96*32;i+=256) sM[i]=0.f;
    __syncthreads();
    for (int ch=0; ch<32; ch++){
        int tok0 = b*SEQ + ch*64;
        for (int i=tid;i<64*96;i+=256){
            int s = i/96, dd = i%96;
            int gi = (tok0+s)*(NMH*HDH) + n*HDH + dd;
            sQ[i] = q[gi];
            sK[i] = kk[gi] * g[(tok0+s)*NMH + n];
        }
        for (int i=tid;i<64*32;i+=256){
            int s=i/32, m=i%32;
            sV[i] = v[(tok0+s)*(NMH*MDH) + n*MDH + m0 + m];
        }
        __syncthreads();
        for (int o=tid;o<64*32;o+=256){
            int s=o/32, m=o%32;
            float acc=0.f;
            const float* qs = sQ + s*96;
            #pragma unroll 8
            for (int dd=0; dd<96; dd++) acc += qs[dd]*sM[dd*32+m];
            reads[(tok0+s)*(NMH*MDH) + n*MDH + m0 + m] = acc;
        }
        __syncthreads();
        float gav = ga[(b*32+ch)*NMH + n];
        for (int e=tid;e<96*32;e+=256){
            int dd=e/32, m=e%32;
            float acc = (1.f-gav)*sM[e];
            #pragma unroll 8
            for (int s=0;s<64;s++) acc += sK[s*96+dd]*sV[s*32+m];
            sM[e]=acc;
        }
        __syncthreads();
    }
}

// ---------------- SIMT fp32 GEMM (router, N=12) ----------------
template<bool BIAS, bool ACC, int ACT>
__global__ __launch_bounds__(256) void sgemm(
    const float* __restrict__ A, const float* __restrict__ B,
    const float* __restrict__ bias, float* __restrict__ C,
    int M, int N, int K, int lda, int ldb, int ldc,
    long sA, long sB, long sC)
{
    __shared__ __align__(16) float As[8*128];
    __shared__ __align__(16) float Bs[8*128];
    A += (long)blockIdx.z * sA;
    B += (long)blockIdx.z * sB;
    C += (long)blockIdx.z * sC;
    int tid = threadIdx.x;
    int row0 = blockIdx.y * 128;
    int col0 = blockIdx.x * 128;
    int tr4 = (tid >> 4) * 4;
    int tc4 = (tid & 15) * 4;
    int arow = tid >> 1, acol = (tid & 1) * 4;
    int brow = tid >> 5, bcol = (tid & 31) * 4;
    const float* Aptr = A + (long)(row0 + arow)*lda + acol;
    const float* Bptr = B + (long)brow*ldb + col0 + bcol;
    bool bvalid = (col0 + bcol + 3) < N;
    float acc[8][8];
    #pragma unroll
    for (int i=0;i<8;i++)
        #pragma unroll
        for (int j=0;j<8;j++) acc[i][j]=0.f;

    for (int k0=0;k0<K;k0+=8){
        float4 av = *(const float4*)Aptr;
        As[(acol+0)*128 + arow]=av.x;
        As[(acol+1)*128 + arow]=av.y;
        As[(acol+2)*128 + arow]=av.z;
        As[(acol+3)*128 + arow]=av.w;
        float4 bv = bvalid ? *(const float4*)Bptr : make_float4(0.f,0.f,0.f,0.f);
        *(float4*)&Bs[brow*128 + bcol] = bv;
        __syncthreads();
        #pragma unroll
        for (int k=0;k<8;k++){
            float4 a0 = *(const float4*)&As[k*128 + tr4];
            float4 a1 = *(const float4*)&As[k*128 + tr4 + 64];
            float4 b0 = *(const float4*)&Bs[k*128 + tc4];
            float4 b1 = *(const float4*)&Bs[k*128 + tc4 + 64];
            float ra[8] = {a0.x,a0.y,a0.z,a0.w,a1.x,a1.y,a1.z,a1.w};
            float rb[8] = {b0.x,b0.y,b0.z,b0.w,b1.x,b1.y,b1.z,b1.w};
            #pragma unroll
            for (int i=0;i<8;i++)
                #pragma unroll
                for (int j=0;j<8;j++) acc[i][j] += ra[i]*rb[j];
        }
        __syncthreads();
        Aptr += 8;
        Bptr += 8*(long)ldb;
    }
    #pragma unroll
    for (int i=0;i<8;i++){
        int r = row0 + tr4 + (i<4 ? i : i-4+64);
        #pragma unroll
        for (int j=0;j<8;j++){
            int cN = col0 + tc4 + (j<4 ? j : j-4+64);
            if (cN < N){
                float v = acc[i][j];
                if (BIAS) v += bias[cN];
                if (ACC)  v += C[(long)r*ldc + cN];
                if (ACT==1) v = 1.f/(1.f+expf(-v));
                C[(long)r*ldc + cN] = v;
            }
        }
    }
}

// ---------------- tf32 tensor-core GEMM (proven core) ----------------
// EPI: 0 plain, 1 resid C=E+gate[r]*(acc+bias), 2 mulsig C=E*sig(acc+bias),
//      3 C+=acc, 4 GLU pairs: C[r][cN/2] = acc_even*sig(acc_odd)  (ldc = N/2)
#define AST 20
#define BST 136
template<bool BIAS, int EPI>
__global__ __launch_bounds__(256) void tgemm(
    const float* __restrict__ A, const float* __restrict__ B,
    const float* __restrict__ bias, float* __restrict__ C,
    const float* __restrict__ E, const float* __restrict__ gate,
    int M, int N, int K, int lda, int ldb, int ldc,
    long sA, long sB, long sC)
{
    __shared__ __align__(16) float As[2][128*AST];
    __shared__ __align__(16) float Bs[2][16*BST];

    A += (long)blockIdx.z * sA;
    B += (long)blockIdx.z * sB;
    C += (long)blockIdx.z * sC;
    if (EPI == 1 || EPI == 2) E += (long)blockIdx.z * sC;

    const int tid  = threadIdx.x;
    const int lane = tid & 31;
    const int wid  = tid >> 5;
    const int wm   = (wid >> 2) * 64;
    const int wn   = (wid & 3) * 32;
    const int qr   = lane >> 2;
    const int qc   = lane & 3;

    const int row0 = blockIdx.y * 128;
    const int col0 = blockIdx.x * 128;

    const int ar = tid >> 2;
    const int ac = (tid & 3) * 4;
    const int bk = tid >> 5;
    const int bn = lane * 4;
    const bool bok = (col0 + bn + 3) < N;

    const float* Ag = A + (long)(row0 + ar)*lda + ac;
    const float* Bg = B + (long)bk*ldb + col0 + bn;

    float acc[4][4][4];
    #pragma unroll
    for (int i=0;i<4;i++)
        #pragma unroll
        for (int j=0;j<4;j++)
            #pragma unroll
            for (int e=0;e<4;e++) acc[i][j][e]=0.f;

    const int nt = K >> 4;
    float4 pa0, pa1, pb0, pb1;

    pa0 = *(const float4*)(Ag);
    pa1 = *(const float4*)(Ag + 64*(long)lda);
    pb0 = bok ? *(const float4*)(Bg)               : make_float4(0,0,0,0);
    pb1 = bok ? *(const float4*)(Bg + 8*(long)ldb) : make_float4(0,0,0,0);
    {
        float* as = As[0]; float* bs = Bs[0];
        as[ar*AST + ac+0] = f2tf32(pa0.x); as[ar*AST + ac+1] = f2tf32(pa0.y);
        as[ar*AST + ac+2] = f2tf32(pa0.z); as[ar*AST + ac+3] = f2tf32(pa0.w);
        as[(ar+64)*AST + ac+0] = f2tf32(pa1.x); as[(ar+64)*AST + ac+1] = f2tf32(pa1.y);
        as[(ar+64)*AST + ac+2] = f2tf32(pa1.z); as[(ar+64)*AST + ac+3] = f2tf32(pa1.w);
        bs[bk*BST + bn+0] = f2tf32(pb0.x); bs[bk*BST + bn+1] = f2tf32(pb0.y);
        bs[bk*BST + bn+2] = f2tf32(pb0.z); bs[bk*BST + bn+3] = f2tf32(pb0.w);
        bs[(bk+8)*BST + bn+0] = f2tf32(pb1.x); bs[(bk+8)*BST + bn+1] = f2tf32(pb1.y);
        bs[(bk+8)*BST + bn+2] = f2tf32(pb1.z); bs[(bk+8)*BST + bn+3] = f2tf32(pb1.w);
    }
    __syncthreads();

    for (int t=0; t<nt; t++){
        int cur = t & 1;
        if (t+1 < nt){
            const float* ag = Ag + (t+1)*16;
            const float* bg = Bg + (long)(t+1)*16*ldb;
            pa0 = *(const float4*)(ag);
            pa1 = *(const float4*)(ag + 64*(long)lda);
            pb0 = bok ? *(const float4*)(bg)               : make_float4(0,0,0,0);
            pb1 = bok ? *(const float4*)(bg + 8*(long)ldb) : make_float4(0,0,0,0);
        }
        const float* as = As[cur];
        const float* bs = Bs[cur];
        #pragma unroll
        for (int ks=0; ks<2; ks++){
            uint32_t af[4][4], bf[4][2];
            #pragma unroll
            for (int i=0;i<4;i++){
                int rbase = (wm + i*16 + qr)*AST + ks*8 + qc;
                af[i][0] = __float_as_uint(as[rbase]);
                af[i][1] = __float_as_uint(as[rbase + 8*AST]);
                af[i][2] = __float_as_uint(as[rbase + 4]);
                af[i][3] = __float_as_uint(as[rbase + 8*AST + 4]);
            }
            #pragma unroll
            for (int j=0;j<4;j++){
                int cb = wn + j*8 + qr;
                bf[j][0] = __float_as_uint(bs[(ks*8 + qc)*BST + cb]);
                bf[j][1] = __float_as_uint(bs[(ks*8 + qc + 4)*BST + cb]);
            }
            #pragma unroll
            for (int i=0;i<4;i++)
                #pragma unroll
                for (int j=0;j<4;j++){
                    asm volatile(
                        "mma.sync.aligned.m16n8k8.row.col.f32.tf32.tf32.f32 "
                        "{%0,%1,%2,%3},{%4,%5,%6,%7},{%8,%9},{%0,%1,%2,%3};"
                        : "+f"(acc[i][j][0]), "+f"(acc[i][j][1]),
                          "+f"(acc[i][j][2]), "+f"(acc[i][j][3])
                        : "r"(af[i][0]), "r"(af[i][1]), "r"(af[i][2]), "r"(af[i][3]),
                          "r"(bf[j][0]), "r"(bf[j][1]));
                }
        }
        if (t+1 < nt){
            float* asw = As[1-cur]; float* bsw = Bs[1-cur];
            asw[ar*AST + ac+0] = f2tf32(pa0.x); asw[ar*AST + ac+1] = f2tf32(pa0.y);
            asw[ar*AST + ac+2] = f2tf32(pa0.z); asw[ar*AST + ac+3] = f2tf32(pa0.w);
            asw[(ar+64)*AST + ac+0] = f2tf32(pa1.x); asw[(ar+64)*AST + ac+1] = f2tf32(pa1.y);
            asw[(ar+64)*AST + ac+2] = f2tf32(pa1.z); asw[(ar+64)*AST + ac+3] = f2tf32(pa1.w);
            bsw[bk*BST + bn+0] = f2tf32(pb0.x); bsw[bk*BST + bn+1] = f2tf32(pb0.y);
            bsw[bk*BST + bn+2] = f2tf32(pb0.z); bsw[bk*BST + bn+3] = f2tf32(pb0.w);
            bsw[(bk+8)*BST + bn+0] = f2tf32(pb1.x); bsw[(bk+8)*BST + bn+1] = f2tf32(pb1.y);
            bsw[(bk+8)*BST + bn+2] = f2tf32(pb1.z); bsw[(bk+8)*BST + bn+3] = f2tf32(pb1.w);
        }
        __syncthreads();
    }

    // epilogue
    #pragma unroll
    for (int i=0;i<4;i++){
        int r0 = row0 + wm + i*16 + qr;
        float gg0 = 0.f, gg1 = 0.f;
        if (EPI == 1){ gg0 = gate[r0]; gg1 = gate[r0+8]; }
        #pragma unroll
        for (int j=0;j<4;j++){
            int cN = col0 + wn + j*8 + qc*2;
            if (cN < N){
                float bv0 = BIAS ? bias[cN]   : 0.f;
                float bv1 = BIAS ? bias[cN+1] : 0.f;
                float v0 = acc[i][j][0] + bv0;
                float v1 = acc[i][j][1] + bv1;
                float v2 = acc[i][j][2] + bv0;
                float v3 = acc[i][j][3] + bv1;
                if (EPI == 4){
                    long p0 = (long)r0*ldc + (cN>>1);
                    long p1 = (long)(r0+8)*ldc + (cN>>1);
                    C[p0] = v0*sigmoidf_(v1);
                    C[p1] = v2*sigmoidf_(v3);
                } else {
                    long o00 = (long)r0*ldc + cN;
                    long o10 = (long)(r0+8)*ldc + cN;
                    if (EPI == 1){
                        v0 = E[o00]   + gg0*v0;
                        v1 = E[o00+1] + gg0*v1;
                        v2 = E[o10]   + gg1*v2;
                        v3 = E[o10+1] + gg1*v3;
                    } else if (EPI == 2){
                        v0 = E[o00]  *sigmoidf_(v0);
                        v1 = E[o00+1]*sigmoidf_(v1);
                        v2 = E[o10]  *sigmoidf_(v2);
                        v3 = E[o10+1]*sigmoidf_(v3);
                    } else if (EPI == 3){
                        v0 += C[o00]; v1 += C[o00+1]; v2 += C[o10]; v3 += C[o10+1];
                    }
                    C[o00]   = v0;
                    C[o00+1] = v1;
                    C[o10]   = v2;
                    C[o10+1] = v3;
                }
            }
        }
    }
}

// ---------------- host ----------------
extern "C" void kernel_launch(void* const* d_in, const int* in_sizes, int n_in,
                              void* d_out, int out_size)
{
    const float* x          = (const float*)d_in[0];
    const float* norm1_w    = (const float*)d_in[1];
    const float* norm2_w    = (const float*)d_in[2];
    const float* norm3_w    = (const float*)d_in[3];
    const float* cs_w       = (const float*)d_in[4];
    const float* cs_b       = (const float*)d_in[5];
    const float* cs_proj_w  = (const float*)d_in[6];
    const float* cs_proj_b  = (const float*)d_in[7];
    const float* gate_proj_w= (const float*)d_in[8];
    const float* router_w   = (const float*)d_in[9];
    const float* router_b   = (const float*)d_in[10];
    const float* head_w     = (const float*)d_in[11];
    const float* head_b     = (const float*)d_in[12];
    const float* mem_q      = (const float*)d_in[13];
    const float* mem_k      = (const float*)d_in[14];
    const float* mem_v      = (const float*)d_in[15];
    const float* mem_gw     = (const float*)d_in[16];
    const float* mem_gb     = (const float*)d_in[17];
    const float* mem_out    = (const float*)d_in[18];
    const float* mixgate_w  = (const float*)d_in[19];
    const float* mixgate_b  = (const float*)d_in[20];
    const float* mixing_w   = (const float*)d_in[21];
    const float* mixing_b   = (const float*)d_in[22];
    const float* ffn_in_w   = (const float*)d_in[23];
    const float* ffn_out_w  = (const float*)d_in[24];
    const float* cg_w       = (const float*)d_in[25];
    const float* cg_b       = (const float*)d_in[26];
    const float* sg_w       = (const float*)d_in[27];
    const float* sg_b       = (const float*)d_in[28];
    const float* fg_w       = (const float*)d_in[29];
    const float* fg_b       = (const float*)d_in[30];

    float *X,*A,*Bb,*C,*D,*GLU,*Q,*Kb,*V,*R,*G,*GA,*GATE,*HW,*WPGP,*WPFI;
    cudaGetSymbolAddress((void**)&X,  g_x);
    cudaGetSymbolAddress((void**)&A,  g_a);
    cudaGetSymbolAddress((void**)&Bb, g_b);
    cudaGetSymbolAddress((void**)&C,  g_c);
    cudaGetSymbolAddress((void**)&D,  g_d);
    cudaGetSymbolAddress((void**)&GLU,g_glu);
    cudaGetSymbolAddress((void**)&Q,  g_q);
    cudaGetSymbolAddress((void**)&Kb, g_k);
    cudaGetSymbolAddress((void**)&V,  g_v);
    cudaGetSymbolAddress((void**)&R,  g_r);
    cudaGetSymbolAddress((void**)&G,  g_g);
    cudaGetSymbolAddress((void**)&GA, g_ga);
    cudaGetSymbolAddress((void**)&GATE,g_gate);
    cudaGetSymbolAddress((void**)&HW, g_hw);
    cudaGetSymbolAddress((void**)&WPGP, g_wp_gp);
    cudaGetSymbolAddress((void**)&WPFI, g_wp_fi);

    cudaFuncSetAttribute(scan_kernel, cudaFuncAttributeMaxDynamicSharedMemorySize, 69632);

    const int EB4 = TOTAL/4/256;   // 9216

    // ===== weight pair-permutes for fused GLU =====
    permute_pair<<<(1152L*2304+255)/256,256>>>(gate_proj_w, WPGP, 1152L*2304, 2304);
    permute_pair<<<(1152L*9216+255)/256,256>>>(ffn_in_w,  WPFI, 1152L*9216, 9216);

    // ===== stage 1: conv stack =====
    rms_gate_kernel<<<NTOK,256>>>(x, norm1_w, cg_w, cg_b, A, GATE);
    {
        const int dil[6] = {1,2,4,8,16,32};
        float* pin = A; float* pout = Bb;
        for (int i=0;i<6;i++){
            conv_cs_kernel<<<EB4,256>>>((const float4*)pin, (float4*)pout,
                (const float4*)(cs_w + i*HDIM*4), (const float4*)(cs_b + i*HDIM), dil[i]);
            float* tmp = pin; pin = pout; pout = tmp;
        }
    }
    // X = x + gate*(A@cs_proj + b)
    tgemm<true,1><<<dim3(9,64,1),256>>>(A, cs_proj_w, cs_proj_b, X, x, GATE,
        NTOK, HDIM, HDIM, HDIM, HDIM, HDIM, 0,0,0);

    // ===== stage 2: multi-head state =====
    rms_gate_kernel<<<NTOK,256>>>(X, norm2_w, sg_w, sg_b, A, GATE);
    sgemm<true,false,1><<<dim3(1,64,1),256>>>(A, router_w, router_b, HW,
        NTOK, 12, HDIM, HDIM, 12, 12, 0,0,0);
    // Bb = glu(A @ gate_proj)  (fused via pair-interleaved weights)
    tgemm<false,4><<<dim3(18,64,1),256>>>(A, WPGP, nullptr, Bb, nullptr, nullptr,
        NTOK, 2304, HDIM, HDIM, 2304, HDIM, 0,0,0);
    memg_kernel<<<NTOK,128>>>(Bb, mem_gw, mem_gb, G);
    ga_kernel<<<2,256>>>(G, GA);
    tgemm<false,0><<<dim3(1,64,4),256>>>(Bb + 6*HDH, mem_q, nullptr, Q, nullptr, nullptr,
        NTOK, HDH, HDH, HDIM, HDH, NMH*HDH, HDH, HDH*HDH, HDH);
    tgemm<false,0><<<dim3(1,64,4),256>>>(Bb + 6*HDH, mem_k, nullptr, Kb, nullptr, nullptr,
        NTOK, HDH, HDH, HDIM, HDH, NMH*HDH, HDH, HDH*HDH, HDH);
    tgemm<false,0><<<dim3(1,64,4),256>>>(Bb + 6*HDH, mem_v, nullptr, V, nullptr, nullptr,
        NTOK, MDH, HDH, HDIM, MDH, NMH*MDH, HDH, HDH*MDH, MDH);
    conv_head_kernel<<<EB4,256>>>((const float4*)Bb, (float4*)C, (const float4*)head_w, head_b, 0);
    conv_head_kernel<<<EB4,256>>>((const float4*)C,  (float4*)A, (const float4*)head_w, head_b, 1);
    conv_head_kernel<<<EB4,256>>>((const float4*)A,  (float4*)C, (const float4*)head_w, head_b, 2);
    scan_kernel<<<dim3(16,4),256,69632>>>(Q, Kb, V, G, GA, R);
    // C[:, memheads] += R @ mem_out
    tgemm<false,3><<<dim3(1,64,4),256>>>(R, mem_out, nullptr, C + 6*HDH, nullptr, nullptr,
        NTOK, HDH, MDH, NMH*MDH, HDH, HDIM, MDH, MDH*HDH, HDH);
    hwmul_kernel<<<EB4,256>>>((float4*)C, HW);
    // D = C * sigmoid(C@mixgate + b)
    tgemm<true,2><<<dim3(9,64,1),256>>>(C, mixgate_w, mixgate_b, D, C, nullptr,
        NTOK, HDIM, HDIM, HDIM, HDIM, HDIM, 0,0,0);
    // X = X + gate*(D@mixing + b)
    tgemm<true,1><<<dim3(9,64,1),256>>>(D, mixing_w, mixing_b, X, X, GATE,
        NTOK, HDIM, HDIM, HDIM, HDIM, HDIM, 0,0,0);

    // ===== stage 3: GLU FFN =====
    rms_gate_kernel<<<NTOK,256>>>(X, norm3_w, fg_w, fg_b, A, GATE);
    // GLU = glu(A @ ffn_in)  (fused)
    tgemm<false,4><<<dim3(72,64,1),256>>>(A, WPFI, nullptr, GLU, nullptr, nullptr,
        NTOK, 9216, HDIM, HDIM, 9216, INNERD, 0,0,0);
    // out = X + gate*(GLU@ffn_out)
    tgemm<false,1><<<dim3(9,64,1),256>>>(GLU, ffn_out_w, nullptr, (float*)d_out, X, GATE,
        NTOK, HDIM, INNERD, INNERD, HDIM, HDIM, 0,0,0);

    (void)in_sizes; (void)n_in; (void)out_size;
}

// round 8
// speedup vs baseline: 2.5202x; 1.1120x over previous
#include <cuda_runtime.h>
#include <math.h>
#include <stdint.h>

#define NTOK  8192      // B*S
#define HDIM  1152
#define TOTAL (NTOK*HDIM)
#define SEQ   2048
#define INNERD 4608
#define NMH   4
#define HDH   96
#define MDH   128
#define H4    (HDIM/4)   // 288

// ---------------- scratch (device globals; no allocs allowed) ----------------
__device__ float g_x  [TOTAL];
__device__ float g_a  [TOTAL];
__device__ float g_b  [TOTAL];
__device__ float g_c  [TOTAL];
__device__ float g_d  [TOTAL];
__device__ float g_glu[NTOK*INNERD];
__device__ float g_q  [NTOK*NMH*HDH];
__device__ float g_k  [NTOK*NMH*HDH];
__device__ float g_v  [NTOK*NMH*MDH];
__device__ float g_r  [NTOK*NMH*MDH];
__device__ float g_g  [NTOK*NMH];
__device__ float g_ga [4*32*NMH];
__device__ float g_gate[NTOK];
__device__ float g_hw [NTOK*12];
// pair-interleaved weights for fused GLU epilogue
__device__ float g_wp_gp [1152*2304];
__device__ float g_wp_fi [1152*9216];
// tap-major conv weights
__device__ float g_cs_wt [6*4*1152];
__device__ float g_hd_wt [36*4*96];

__constant__ int c_head_dil[12][3] = {
  {1,2,4},{1,1,1},{4,8,16},{8,16,32},{32,64,128},{64,128,256},
  {256,512,1024},{1,100,200},{1,500,1000},{1,1024,2048},{3,9,27},{5,25,125}
};

__device__ __forceinline__ float sigmoidf_(float x){ return 1.f/(1.f+__expf(-x)); }
__device__ __forceinline__ float f2tf32(float f){
    uint32_t r; asm("cvt.rna.tf32.f32 %0,%1;" : "=r"(r) : "f"(f));
    return __uint_as_float(r);
}

// ---------------- column pair-interleave: out[k][2m]=in[k][m], out[k][2m+1]=in[k][half+m]
__global__ void permute_pair(const float* __restrict__ in, float* __restrict__ out, long total, int N)
{
    long idx = (long)blockIdx.x*256 + threadIdx.x;
    if (idx >= total) return;
    long k = idx / N;
    int  j = (int)(idx % N);
    int  h = N >> 1;
    out[idx] = in[k*N + ((j & 1) ? h + (j >> 1) : (j >> 1))];
}

// ---------------- conv weight transpose to tap-major ----------------
__global__ void wtrans_kernel(const float* __restrict__ cs_w, const float* __restrict__ head_w,
                              float* __restrict__ cs_wt, float* __restrict__ head_wt)
{
    int idx = blockIdx.x*256 + threadIdx.x;
    if (idx < 6*4*1152){
        int i = idx / (4*1152);
        int r = idx % (4*1152);
        int j = r / 1152;
        int c = r % 1152;
        cs_wt[idx] = cs_w[(i*1152 + c)*4 + j];
    }
    if (idx < 36*4*96){
        int hl = idx / (4*96);
        int r  = idx % (4*96);
        int j  = r / 96;
        int c  = r % 96;
        head_wt[idx] = head_w[(hl*96 + c)*4 + j];
    }
}

// ---------------- fused rmsnorm + token scalar gate (float4) ----------------
__global__ void rms_gate_kernel(const float* __restrict__ x, const float* __restrict__ nw,
                                const float* __restrict__ gw, const float* __restrict__ gb,
                                float* __restrict__ xn, float* __restrict__ gate)
{
    __shared__ float s1[8], s2[8], sinv;
    int t = blockIdx.x;
    const float4* xr = (const float4*)(x + (long)t*HDIM);
    const float4* gw4 = (const float4*)gw;
    const float4* nw4 = (const float4*)nw;
    float4 vbuf[2];
    float ss=0.f, dg=0.f;
    int nit = 0;
    for (int c=threadIdx.x; c<H4; c+=256){
        float4 v = xr[c]; vbuf[nit++] = v;
        float4 w = gw4[c];
        ss += v.x*v.x + v.y*v.y + v.z*v.z + v.w*v.w;
        dg += v.x*w.x + v.y*w.y + v.z*w.z + v.w*w.w;
    }
    for (int o=16;o;o>>=1){ ss+=__shfl_down_sync(~0u,ss,o); dg+=__shfl_down_sync(~0u,dg,o); }
    int w=threadIdx.x>>5, l=threadIdx.x&31;
    if (l==0){ s1[w]=ss; s2[w]=dg; }
    __syncthreads();
    if (threadIdx.x==0){
        float a=0,bq=0;
        #pragma unroll
        for (int i=0;i<8;i++){ a+=s1[i]; bq+=s2[i]; }
        sinv = rsqrtf(a/(float)HDIM + 1e-6f);
        gate[t] = 1.f/(1.f+expf(-(bq+gb[0])));
    }
    __syncthreads();
    float inv = sinv;
    float4* xo = (float4*)(xn + (long)t*HDIM);
    nit = 0;
    for (int c=threadIdx.x; c<H4; c+=256){
        float4 v = vbuf[nit++];
        float4 nwv = nw4[c];
        xo[c] = make_float4(v.x*inv*nwv.x, v.y*inv*nwv.y, v.z*inv*nwv.z, v.w*inv*nwv.w);
    }
}

// ---------------- conv stack layer (float4, tap-major weights) ----------------
__global__ void conv_cs_kernel(const float4* __restrict__ in, float4* __restrict__ out,
                               const float* __restrict__ wt, const float4* __restrict__ bias4, int d)
{
    int idx = blockIdx.x*256 + threadIdx.x;
    if (idx >= TOTAL/4) return;
    int c4 = idx % H4;
    int t  = idx / H4;
    int s  = t & (SEQ-1);
    float4 wj[4];
    #pragma unroll
    for (int j=0;j<4;j++) wj[j] = ((const float4*)(wt + j*HDIM))[c4];
    float4 b4 = bias4[c4];
    float acc[4] = {b4.x, b4.y, b4.z, b4.w};
    #pragma unroll
    for (int j=0;j<4;j++){
        int sp = s - (3-j)*d;
        if (sp >= 0){
            float4 xv = in[idx + (sp - s)*H4];
            acc[0] += wj[j].x*xv.x;
            acc[1] += wj[j].y*xv.y;
            acc[2] += wj[j].z*xv.z;
            acc[3] += wj[j].w*xv.w;
        }
    }
    float4 iv = in[idx];
    float4 ov;
    ov.x = iv.x + 0.5f*acc[0]*(1.f + erff(acc[0]*0.70710678118654752f));
    ov.y = iv.y + 0.5f*acc[1]*(1.f + erff(acc[1]*0.70710678118654752f));
    ov.z = iv.z + 0.5f*acc[2]*(1.f + erff(acc[2]*0.70710678118654752f));
    ov.w = iv.w + 0.5f*acc[3]*(1.f + erff(acc[3]*0.70710678118654752f));
    out[idx] = ov;
}

// ---------------- head conv layer (float4, tap-major weights) ----------------
__global__ void conv_head_kernel(const float4* __restrict__ in, float4* __restrict__ out,
                                 const float* __restrict__ hwt, const float* __restrict__ hb, int layer)
{
    int idx = blockIdx.x*256 + threadIdx.x;
    if (idx >= TOTAL/4) return;
    int c4 = idx % H4;
    int t  = idx / H4;
    int s  = t & (SEQ-1);
    int ch = c4*4;
    int head = ch / HDH;
    int cin  = ch % HDH;
    int d = c_head_dil[head][layer];
    int hl = head*3 + layer;
    float4 wj[4];
    #pragma unroll
    for (int j=0;j<4;j++) wj[j] = ((const float4*)(hwt + (hl*4 + j)*HDH))[cin>>2];
    float4 b4 = ((const float4*)hb)[(hl*HDH + cin)>>2];
    float acc[4] = {b4.x, b4.y, b4.z, b4.w};
    #pragma unroll
    for (int j=0;j<4;j++){
        int sp = s - (3-j)*d;
        if (sp >= 0){
            float4 xv = in[idx + (sp - s)*H4];
            acc[0] += wj[j].x*xv.x;
            acc[1] += wj[j].y*xv.y;
            acc[2] += wj[j].z*xv.z;
            acc[3] += wj[j].w*xv.w;
        }
    }
    float4 iv = in[idx];
    out[idx] = make_float4(iv.x+acc[0], iv.y+acc[1], iv.z+acc[2], iv.w+acc[3]);
}

// ---------------- hw mul (float4) ----------------
__global__ void hwmul_kernel(float4* __restrict__ a, const float* __restrict__ hw)
{
    int idx = blockIdx.x*256 + threadIdx.x;
    if (idx >= TOTAL/4) return;
    int t = idx / H4, h = (idx % H4)*4/HDH;
    float g = hw[t*12 + h];
    float4 v = a[idx];
    a[idx] = make_float4(v.x*g, v.y*g, v.z*g, v.w*g);
}

// ---------------- memory-head gate g and chunk means ----------------
__global__ void memg_kernel(const float* __restrict__ xg, const float* __restrict__ gw,
                            const float* __restrict__ gb, float* __restrict__ g)
{
    int t = blockIdx.x;
    int warp = threadIdx.x >> 5, lane = threadIdx.x & 31;
    const float* xr = xg + (long)t*HDIM + (6+warp)*HDH;
    const float* w  = gw + warp*HDH;
    float acc = 0.f;
    for (int c=lane;c<HDH;c+=32) acc += xr[c]*w[c];
    for (int o=16;o;o>>=1) acc += __shfl_down_sync(~0u,acc,o);
    if (lane==0) g[t*NMH+warp] = 1.f/(1.f+expf(-(acc + gb[warp])));
}

__global__ void ga_kernel(const float* __restrict__ g, float* __restrict__ ga)
{
    int e = blockIdx.x*256 + threadIdx.x;
    if (e >= 4*32*NMH) return;
    int n = e % NMH, ch = (e/NMH) % 32, b = e/(NMH*32);
    int base = (b*SEQ + ch*64)*NMH + n;
    float s = 0.f;
    for (int i=0;i<64;i++) s += g[base + i*NMH];
    ga[e] = s*(1.f/64.f);
}

// ---------------- chunked fast-weight scan (register-tiled) ----------------
// grid (16, 4), 256 threads, dyn smem 69632
__global__ void scan_kernel(const float* __restrict__ q, const float* __restrict__ kk,
                            const float* __restrict__ v, const float* __restrict__ g,
                            const float* __restrict__ ga, float* __restrict__ reads)
{
    extern __shared__ float smx[];
    float* sM = smx;             // 96*32
    float* sQ = sM + 96*32;      // 64*96
    float* sK = sQ + 64*96;      // 64*96
    float* sV = sK + 64*96;      // 64*32
    float4* sM4 = (float4*)sM;
    float4* sV4 = (float4*)sV;
    int bn = blockIdx.x;
    int b = bn >> 2, n = bn & 3;
    int m0 = blockIdx.y * 32;
    int tid = threadIdx.x;
    const int dd0 = (tid >> 3) * 3;   // 0,3,...,93
    const int mg  = tid & 7;          // m-group (4 cols each)

    for (int i=tid;i<96*32;i+=256) sM[i]=0.f;
    __syncthreads();
    for (int ch=0; ch<32; ch++){
        int tok0 = b*SEQ + ch*64;
        // load sQ and sK=k*g (64x96) as float4
        for (int i=tid; i<64*24; i+=256){
            int s = i/24, cc = i%24;
            long base = (long)(tok0+s)*(NMH*HDH) + n*HDH;
            float gv = g[(tok0+s)*NMH + n];
            float4 qv = ((const float4*)(q + base))[cc];
            float4 kv = ((const float4*)(kk + base))[cc];
            ((float4*)sQ)[i] = qv;
            ((float4*)sK)[i] = make_float4(kv.x*gv, kv.y*gv, kv.z*gv, kv.w*gv);
        }
        // load sV (64x32) as float4
        for (int i=tid; i<64*8; i+=256){
            int s = i/8, mm = i%8;
            sV4[i] = ((const float4*)(v + (long)(tok0+s)*(NMH*MDH) + n*MDH + m0))[mm];
        }
        __syncthreads();
        // reads with OLD M: 512 items (s, m-group), 2 per thread
        #pragma unroll
        for (int it=0; it<2; it++){
            int item = tid + it*256;
            int s = item >> 3, mgg = item & 7;
            const float* qs = sQ + s*96;
            float4 acc = make_float4(0.f,0.f,0.f,0.f);
            #pragma unroll 4
            for (int dd=0; dd<96; dd++){
                float qv = qs[dd];
                float4 mv = sM4[dd*8 + mgg];
                acc.x += qv*mv.x; acc.y += qv*mv.y; acc.z += qv*mv.z; acc.w += qv*mv.w;
            }
            ((float4*)(reads + (long)(tok0+s)*(NMH*MDH) + n*MDH + m0))[mgg] = acc;
        }
        __syncthreads();
        // update M: each thread owns 3 dd rows x 4 m cols
        float gav = ga[(b*32+ch)*NMH + n];
        float om = 1.f - gav;
        float4 a0 = sM4[(dd0+0)*8+mg];
        float4 a1 = sM4[(dd0+1)*8+mg];
        float4 a2 = sM4[(dd0+2)*8+mg];
        a0.x*=om; a0.y*=om; a0.z*=om; a0.w*=om;
        a1.x*=om; a1.y*=om; a1.z*=om; a1.w*=om;
        a2.x*=om; a2.y*=om; a2.z*=om; a2.w*=om;
        __syncthreads();   // all old-M reads done before any writes
        #pragma unroll 2
        for (int s=0;s<64;s++){
            const float* ks = sK + s*96 + dd0;
            float k0 = ks[0], k1 = ks[1], k2 = ks[2];
            float4 vv = sV4[s*8+mg];
            a0.x += k0*vv.x; a0.y += k0*vv.y; a0.z += k0*vv.z; a0.w += k0*vv.w;
            a1.x += k1*vv.x; a1.y += k1*vv.y; a1.z += k1*vv.z; a1.w += k1*vv.w;
            a2.x += k2*vv.x; a2.y += k2*vv.y; a2.z += k2*vv.z; a2.w += k2*vv.w;
        }
        sM4[(dd0+0)*8+mg] = a0;
        sM4[(dd0+1)*8+mg] = a1;
        sM4[(dd0+2)*8+mg] = a2;
        __syncthreads();
    }
}

// ---------------- SIMT fp32 GEMM (router, N=12) ----------------
template<bool BIAS, bool ACC, int ACT>
__global__ __launch_bounds__(256) void sgemm(
    const float* __restrict__ A, const float* __restrict__ B,
    const float* __restrict__ bias, float* __restrict__ C,
    int M, int N, int K, int lda, int ldb, int ldc,
    long sA, long sB, long sC)
{
    __shared__ __align__(16) float As[8*128];
    __shared__ __align__(16) float Bs[8*128];
    A += (long)blockIdx.z * sA;
    B += (long)blockIdx.z * sB;
    C += (long)blockIdx.z * sC;
    int tid = threadIdx.x;
    int row0 = blockIdx.y * 128;
    int col0 = blockIdx.x * 128;
    int tr4 = (tid >> 4) * 4;
    int tc4 = (tid & 15) * 4;
    int arow = tid >> 1, acol = (tid & 1) * 4;
    int brow = tid >> 5, bcol = (tid & 31) * 4;
    const float* Aptr = A + (long)(row0 + arow)*lda + acol;
    const float* Bptr = B + (long)brow*ldb + col0 + bcol;
    bool bvalid = (col0 + bcol + 3) < N;
    float acc[8][8];
    #pragma unroll
    for (int i=0;i<8;i++)
        #pragma unroll
        for (int j=0;j<8;j++) acc[i][j]=0.f;

    for (int k0=0;k0<K;k0+=8){
        float4 av = *(const float4*)Aptr;
        As[(acol+0)*128 + arow]=av.x;
        As[(acol+1)*128 + arow]=av.y;
        As[(acol+2)*128 + arow]=av.z;
        As[(acol+3)*128 + arow]=av.w;
        float4 bv = bvalid ? *(const float4*)Bptr : make_float4(0.f,0.f,0.f,0.f);
        *(float4*)&Bs[brow*128 + bcol] = bv;
        __syncthreads();
        #pragma unroll
        for (int k=0;k<8;k++){
            float4 a0 = *(const float4*)&As[k*128 + tr4];
            float4 a1 = *(const float4*)&As[k*128 + tr4 + 64];
            float4 b0 = *(const float4*)&Bs[k*128 + tc4];
            float4 b1 = *(const float4*)&Bs[k*128 + tc4 + 64];
            float ra[8] = {a0.x,a0.y,a0.z,a0.w,a1.x,a1.y,a1.z,a1.w};
            float rb[8] = {b0.x,b0.y,b0.z,b0.w,b1.x,b1.y,b1.z,b1.w};
            #pragma unroll
            for (int i=0;i<8;i++)
                #pragma unroll
                for (int j=0;j<8;j++) acc[i][j] += ra[i]*rb[j];
        }
        __syncthreads();
        Aptr += 8;
        Bptr += 8*(long)ldb;
    }
    #pragma unroll
    for (int i=0;i<8;i++){
        int r = row0 + tr4 + (i<4 ? i : i-4+64);
        #pragma unroll
        for (int j=0;j<8;j++){
            int cN = col0 + tc4 + (j<4 ? j : j-4+64);
            if (cN < N){
                float v = acc[i][j];
                if (BIAS) v += bias[cN];
                if (ACC)  v += C[(long)r*ldc + cN];
                if (ACT==1) v = 1.f/(1.f+expf(-v));
                C[(long)r*ldc + cN] = v;
            }
        }
    }
}

// ---------------- tf32 tensor-core GEMM (proven core) ----------------
// EPI: 0 plain, 1 resid C=E+gate[r]*(acc+bias), 2 mulsig C=E*sig(acc+bias),
//      3 C+=acc, 4 GLU pairs: C[r][cN/2] = acc_even*sig(acc_odd)  (ldc = N/2)
#define AST 20
#define BST 136
template<bool BIAS, int EPI>
__global__ __launch_bounds__(256) void tgemm(
    const float* __restrict__ A, const float* __restrict__ B,
    const float* __restrict__ bias, float* __restrict__ C,
    const float* __restrict__ E, const float* __restrict__ gate,
    int M, int N, int K, int lda, int ldb, int ldc,
    long sA, long sB, long sC)
{
    __shared__ __align__(16) float As[2][128*AST];
    __shared__ __align__(16) float Bs[2][16*BST];

    A += (long)blockIdx.z * sA;
    B += (long)blockIdx.z * sB;
    C += (long)blockIdx.z * sC;
    if (EPI == 1 || EPI == 2) E += (long)blockIdx.z * sC;

    const int tid  = threadIdx.x;
    const int lane = tid & 31;
    const int wid  = tid >> 5;
    const int wm   = (wid >> 2) * 64;
    const int wn   = (wid & 3) * 32;
    const int qr   = lane >> 2;
    const int qc   = lane & 3;

    const int row0 = blockIdx.y * 128;
    const int col0 = blockIdx.x * 128;

    const int ar = tid >> 2;
    const int ac = (tid & 3) * 4;
    const int bk = tid >> 5;
    const int bn = lane * 4;
    const bool bok = (col0 + bn + 3) < N;

    const float* Ag = A + (long)(row0 + ar)*lda + ac;
    const float* Bg = B + (long)bk*ldb + col0 + bn;

    float acc[4][4][4];
    #pragma unroll
    for (int i=0;i<4;i++)
        #pragma unroll
        for (int j=0;j<4;j++)
            #pragma unroll
            for (int e=0;e<4;e++) acc[i][j][e]=0.f;

    const int nt = K >> 4;
    float4 pa0, pa1, pb0, pb1;

    pa0 = *(const float4*)(Ag);
    pa1 = *(const float4*)(Ag + 64*(long)lda);
    pb0 = bok ? *(const float4*)(Bg)               : make_float4(0,0,0,0);
    pb1 = bok ? *(const float4*)(Bg + 8*(long)ldb) : make_float4(0,0,0,0);
    {
        float* as = As[0]; float* bs = Bs[0];
        as[ar*AST + ac+0] = f2tf32(pa0.x); as[ar*AST + ac+1] = f2tf32(pa0.y);
        as[ar*AST + ac+2] = f2tf32(pa0.z); as[ar*AST + ac+3] = f2tf32(pa0.w);
        as[(ar+64)*AST + ac+0] = f2tf32(pa1.x); as[(ar+64)*AST + ac+1] = f2tf32(pa1.y);
        as[(ar+64)*AST + ac+2] = f2tf32(pa1.z); as[(ar+64)*AST + ac+3] = f2tf32(pa1.w);
        bs[bk*BST + bn+0] = f2tf32(pb0.x); bs[bk*BST + bn+1] = f2tf32(pb0.y);
        bs[bk*BST + bn+2] = f2tf32(pb0.z); bs[bk*BST + bn+3] = f2tf32(pb0.w);
        bs[(bk+8)*BST + bn+0] = f2tf32(pb1.x); bs[(bk+8)*BST + bn+1] = f2tf32(pb1.y);
        bs[(bk+8)*BST + bn+2] = f2tf32(pb1.z); bs[(bk+8)*BST + bn+3] = f2tf32(pb1.w);
    }
    __syncthreads();

    for (int t=0; t<nt; t++){
        int cur = t & 1;
        if (t+1 < nt){
            const float* ag = Ag + (t+1)*16;
            const float* bg = Bg + (long)(t+1)*16*ldb;
            pa0 = *(const float4*)(ag);
            pa1 = *(const float4*)(ag + 64*(long)lda);
            pb0 = bok ? *(const float4*)(bg)               : make_float4(0,0,0,0);
            pb1 = bok ? *(const float4*)(bg + 8*(long)ldb) : make_float4(0,0,0,0);
        }
        const float* as = As[cur];
        const float* bs = Bs[cur];
        #pragma unroll
        for (int ks=0; ks<2; ks++){
            uint32_t af[4][4], bf[4][2];
            #pragma unroll
            for (int i=0;i<4;i++){
                int rbase = (wm + i*16 + qr)*AST + ks*8 + qc;
                af[i][0] = __float_as_uint(as[rbase]);
                af[i][1] = __float_as_uint(as[rbase + 8*AST]);
                af[i][2] = __float_as_uint(as[rbase + 4]);
                af[i][3] = __float_as_uint(as[rbase + 8*AST + 4]);
            }
            #pragma unroll
            for (int j=0;j<4;j++){
                int cb = wn + j*8 + qr;
                bf[j][0] = __float_as_uint(bs[(ks*8 + qc)*BST + cb]);
                bf[j][1] = __float_as_uint(bs[(ks*8 + qc + 4)*BST + cb]);
            }
            #pragma unroll
            for (int i=0;i<4;i++)
                #pragma unroll
                for (int j=0;j<4;j++){
                    asm volatile(
                        "mma.sync.aligned.m16n8k8.row.col.f32.tf32.tf32.f32 "
                        "{%0,%1,%2,%3},{%4,%5,%6,%7},{%8,%9},{%0,%1,%2,%3};"
                        : "+f"(acc[i][j][0]), "+f"(acc[i][j][1]),
                          "+f"(acc[i][j][2]), "+f"(acc[i][j][3])
                        : "r"(af[i][0]), "r"(af[i][1]), "r"(af[i][2]), "r"(af[i][3]),
                          "r"(bf[j][0]), "r"(bf[j][1]));
                }
        }
        if (t+1 < nt){
            float* asw = As[1-cur]; float* bsw = Bs[1-cur];
            asw[ar*AST + ac+0] = f2tf32(pa0.x); asw[ar*AST + ac+1] = f2tf32(pa0.y);
            asw[ar*AST + ac+2] = f2tf32(pa0.z); asw[ar*AST + ac+3] = f2tf32(pa0.w);
            asw[(ar+64)*AST + ac+0] = f2tf32(pa1.x); asw[(ar+64)*AST + ac+1] = f2tf32(pa1.y);
            asw[(ar+64)*AST + ac+2] = f2tf32(pa1.z); asw[(ar+64)*AST + ac+3] = f2tf32(pa1.w);
            bsw[bk*BST + bn+0] = f2tf32(pb0.x); bsw[bk*BST + bn+1] = f2tf32(pb0.y);
            bsw[bk*BST + bn+2] = f2tf32(pb0.z); bsw[bk*BST + bn+3] = f2tf32(pb0.w);
            bsw[(bk+8)*BST + bn+0] = f2tf32(pb1.x); bsw[(bk+8)*BST + bn+1] = f2tf32(pb1.y);
            bsw[(bk+8)*BST + bn+2] = f2tf32(pb1.z); bsw[(bk+8)*BST + bn+3] = f2tf32(pb1.w);
        }
        __syncthreads();
    }

    // epilogue
    #pragma unroll
    for (int i=0;i<4;i++){
        int r0 = row0 + wm + i*16 + qr;
        float gg0 = 0.f, gg1 = 0.f;
        if (EPI == 1){ gg0 = gate[r0]; gg1 = gate[r0+8]; }
        #pragma unroll
        for (int j=0;j<4;j++){
            int cN = col0 + wn + j*8 + qc*2;
            if (cN < N){
                float bv0 = BIAS ? bias[cN]   : 0.f;
                float bv1 = BIAS ? bias[cN+1] : 0.f;
                float v0 = acc[i][j][0] + bv0;
                float v1 = acc[i][j][1] + bv1;
                float v2 = acc[i][j][2] + bv0;
                float v3 = acc[i][j][3] + bv1;
                if (EPI == 4){
                    long p0 = (long)r0*ldc + (cN>>1);
                    long p1 = (long)(r0+8)*ldc + (cN>>1);
                    C[p0] = v0*sigmoidf_(v1);
                    C[p1] = v2*sigmoidf_(v3);
                } else {
                    long o00 = (long)r0*ldc + cN;
                    long o10 = (long)(r0+8)*ldc + cN;
                    if (EPI == 1){
                        v0 = E[o00]   + gg0*v0;
                        v1 = E[o00+1] + gg0*v1;
                        v2 = E[o10]   + gg1*v2;
                        v3 = E[o10+1] + gg1*v3;
                    } else if (EPI == 2){
                        v0 = E[o00]  *sigmoidf_(v0);
                        v1 = E[o00+1]*sigmoidf_(v1);
                        v2 = E[o10]  *sigmoidf_(v2);
                        v3 = E[o10+1]*sigmoidf_(v3);
                    } else if (EPI == 3){
                        v0 += C[o00]; v1 += C[o00+1]; v2 += C[o10]; v3 += C[o10+1];
                    }
                    C[o00]   = v0;
                    C[o00+1] = v1;
                    C[o10]   = v2;
                    C[o10+1] = v3;
                }
            }
        }
    }
}

// ---------------- host ----------------
extern "C" void kernel_launch(void* const* d_in, const int* in_sizes, int n_in,
                              void* d_out, int out_size)
{
    const float* x          = (const float*)d_in[0];
    const float* norm1_w    = (const float*)d_in[1];
    const float* norm2_w    = (const float*)d_in[2];
    const float* norm3_w    = (const float*)d_in[3];
    const float* cs_w       = (const float*)d_in[4];
    const float* cs_b       = (const float*)d_in[5];
    const float* cs_proj_w  = (const float*)d_in[6];
    const float* cs_proj_b  = (const float*)d_in[7];
    const float* gate_proj_w= (const float*)d_in[8];
    const float* router_w   = (const float*)d_in[9];
    const float* router_b   = (const float*)d_in[10];
    const float* head_w     = (const float*)d_in[11];
    const float* head_b     = (const float*)d_in[12];
    const float* mem_q      = (const float*)d_in[13];
    const float* mem_k      = (const float*)d_in[14];
    const float* mem_v      = (const float*)d_in[15];
    const float* mem_gw     = (const float*)d_in[16];
    const float* mem_gb     = (const float*)d_in[17];
    const float* mem_out    = (const float*)d_in[18];
    const float* mixgate_w  = (const float*)d_in[19];
    const float* mixgate_b  = (const float*)d_in[20];
    const float* mixing_w   = (const float*)d_in[21];
    const float* mixing_b   = (const float*)d_in[22];
    const float* ffn_in_w   = (const float*)d_in[23];
    const float* ffn_out_w  = (const float*)d_in[24];
    const float* cg_w       = (const float*)d_in[25];
    const float* cg_b       = (const float*)d_in[26];
    const float* sg_w       = (const float*)d_in[27];
    const float* sg_b       = (const float*)d_in[28];
    const float* fg_w       = (const float*)d_in[29];
    const float* fg_b       = (const float*)d_in[30];

    float *X,*A,*Bb,*C,*D,*GLU,*Q,*Kb,*V,*R,*G,*GA,*GATE,*HW,*WPGP,*WPFI,*CSWT,*HDWT;
    cudaGetSymbolAddress((void**)&X,  g_x);
    cudaGetSymbolAddress((void**)&A,  g_a);
    cudaGetSymbolAddress((void**)&Bb, g_b);
    cudaGetSymbolAddress((void**)&C,  g_c);
    cudaGetSymbolAddress((void**)&D,  g_d);
    cudaGetSymbolAddress((void**)&GLU,g_glu);
    cudaGetSymbolAddress((void**)&Q,  g_q);
    cudaGetSymbolAddress((void**)&Kb, g_k);
    cudaGetSymbolAddress((void**)&V,  g_v);
    cudaGetSymbolAddress((void**)&R,  g_r);
    cudaGetSymbolAddress((void**)&G,  g_g);
    cudaGetSymbolAddress((void**)&GA, g_ga);
    cudaGetSymbolAddress((void**)&GATE,g_gate);
    cudaGetSymbolAddress((void**)&HW, g_hw);
    cudaGetSymbolAddress((void**)&WPGP, g_wp_gp);
    cudaGetSymbolAddress((void**)&WPFI, g_wp_fi);
    cudaGetSymbolAddress((void**)&CSWT, g_cs_wt);
    cudaGetSymbolAddress((void**)&HDWT, g_hd_wt);

    cudaFuncSetAttribute(scan_kernel, cudaFuncAttributeMaxDynamicSharedMemorySize, 69632);

    const int EB4 = TOTAL/4/256;   // 9216

    // ===== weight preps =====
    permute_pair<<<(1152L*2304+255)/256,256>>>(gate_proj_w, WPGP, 1152L*2304, 2304);
    permute_pair<<<(1152L*9216+255)/256,256>>>(ffn_in_w,  WPFI, 1152L*9216, 9216);
    wtrans_kernel<<<108,256>>>(cs_w, head_w, CSWT, HDWT);

    // ===== stage 1: conv stack =====
    rms_gate_kernel<<<NTOK,256>>>(x, norm1_w, cg_w, cg_b, A, GATE);
    {
        const int dil[6] = {1,2,4,8,16,32};
        float* pin = A; float* pout = Bb;
        for (int i=0;i<6;i++){
            conv_cs_kernel<<<EB4,256>>>((const float4*)pin, (float4*)pout,
                CSWT + i*4*HDIM, (const float4*)(cs_b + i*HDIM), dil[i]);
            float* tmp = pin; pin = pout; pout = tmp;
        }
    }
    // X = x + gate*(A@cs_proj + b)
    tgemm<true,1><<<dim3(9,64,1),256>>>(A, cs_proj_w, cs_proj_b, X, x, GATE,
        NTOK, HDIM, HDIM, HDIM, HDIM, HDIM, 0,0,0);

    // ===== stage 2: multi-head state =====
    rms_gate_kernel<<<NTOK,256>>>(X, norm2_w, sg_w, sg_b, A, GATE);
    sgemm<true,false,1><<<dim3(1,64,1),256>>>(A, router_w, router_b, HW,
        NTOK, 12, HDIM, HDIM, 12, 12, 0,0,0);
    // Bb = glu(A @ gate_proj)  (fused via pair-interleaved weights)
    tgemm<false,4><<<dim3(18,64,1),256>>>(A, WPGP, nullptr, Bb, nullptr, nullptr,
        NTOK, 2304, HDIM, HDIM, 2304, HDIM, 0,0,0);
    memg_kernel<<<NTOK,128>>>(Bb, mem_gw, mem_gb, G);
    ga_kernel<<<2,256>>>(G, GA);
    tgemm<false,0><<<dim3(1,64,4),256>>>(Bb + 6*HDH, mem_q, nullptr, Q, nullptr, nullptr,
        NTOK, HDH, HDH, HDIM, HDH, NMH*HDH, HDH, HDH*HDH, HDH);
    tgemm<false,0><<<dim3(1,64,4),256>>>(Bb + 6*HDH, mem_k, nullptr, Kb, nullptr, nullptr,
        NTOK, HDH, HDH, HDIM, HDH, NMH*HDH, HDH, HDH*HDH, HDH);
    tgemm<false,0><<<dim3(1,64,4),256>>>(Bb + 6*HDH, mem_v, nullptr, V, nullptr, nullptr,
        NTOK, MDH, HDH, HDIM, MDH, NMH*MDH, HDH, HDH*MDH, MDH);
    conv_head_kernel<<<EB4,256>>>((const float4*)Bb, (float4*)C, HDWT, head_b, 0);
    conv_head_kernel<<<EB4,256>>>((const float4*)C,  (float4*)A, HDWT, head_b, 1);
    conv_head_kernel<<<EB4,256>>>((const float4*)A,  (float4*)C, HDWT, head_b, 2);
    scan_kernel<<<dim3(16,4),256,69632>>>(Q, Kb, V, G, GA, R);
    // C[:, memheads] += R @ mem_out
    tgemm<false,3><<<dim3(1,64,4),256>>>(R, mem_out, nullptr, C + 6*HDH, nullptr, nullptr,
        NTOK, HDH, MDH, NMH*MDH, HDH, HDIM, MDH, MDH*HDH, HDH);
    hwmul_kernel<<<EB4,256>>>((float4*)C, HW);
    // D = C * sigmoid(C@mixgate + b)
    tgemm<true,2><<<dim3(9,64,1),256>>>(C, mixgate_w, mixgate_b, D, C, nullptr,
        NTOK, HDIM, HDIM, HDIM, HDIM, HDIM, 0,0,0);
    // X = X + gate*(D@mixing + b)
    tgemm<true,1><<<dim3(9,64,1),256>>>(D, mixing_w, mixing_b, X, X, GATE,
        NTOK, HDIM, HDIM, HDIM, HDIM, HDIM, 0,0,0);

    // ===== stage 3: GLU FFN =====
    rms_gate_kernel<<<NTOK,256>>>(X, norm3_w, fg_w, fg_b, A, GATE);
    // GLU = glu(A @ ffn_in)  (fused)
    tgemm<false,4><<<dim3(72,64,1),256>>>(A, WPFI, nullptr, GLU, nullptr, nullptr,
        NTOK, 9216, HDIM, HDIM, 9216, INNERD, 0,0,0);
    // out = X + gate*(GLU@ffn_out)
    tgemm<false,1><<<dim3(9,64,1),256>>>(GLU, ffn_out_w, nullptr, (float*)d_out, X, GATE,
        NTOK, HDIM, INNERD, INNERD, HDIM, HDIM, 0,0,0);

    (void)in_sizes; (void)n_in; (void)out_size;
}

// round 9
// speedup vs baseline: 2.7540x; 1.0928x over previous
#include <cuda_runtime.h>
#include <math.h>
#include <stdint.h>

#define NTOK  8192      // B*S
#define HDIM  1152
#define TOTAL (NTOK*HDIM)
#define SEQ   2048
#define INNERD 4608
#define NMH   4
#define HDH   96
#define MDH   128
#define H4    (HDIM/4)   // 288

// ---------------- scratch (device globals; no allocs allowed) ----------------
__device__ float g_x  [TOTAL];
__device__ float g_a  [TOTAL];
__device__ float g_b  [TOTAL];
__device__ float g_c  [TOTAL];
__device__ float g_d  [TOTAL];
__device__ float g_glu[NTOK*INNERD];
__device__ float g_q  [NTOK*NMH*HDH];
__device__ float g_k  [NTOK*NMH*HDH];
__device__ float g_v  [NTOK*NMH*MDH];
__device__ float g_r  [NTOK*NMH*MDH];
__device__ float g_g  [NTOK*NMH];
__device__ float g_ga [4*32*NMH];
__device__ float g_gate[NTOK];
__device__ float g_hw [NTOK*12];
// pair-interleaved weights for fused GLU epilogue (tf32 rna-rounded)
__device__ float g_wp_gp [1152*2304];
__device__ float g_wp_fi [1152*9216];
// tap-major conv weights (fp32)
__device__ float g_cs_wt [6*4*1152];
__device__ float g_hd_wt [36*4*96];
// tf32 rna-rounded weight copies (GEMM B operands)
__device__ float g_w_cs [1152*1152];
__device__ float g_w_mg [1152*1152];
__device__ float g_w_mx [1152*1152];
__device__ float g_w_fo [4608*1152];
__device__ float g_w_mq [4*96*96];
__device__ float g_w_mk [4*96*96];
__device__ float g_w_mv [4*96*128];
__device__ float g_w_mo [4*128*96];

__constant__ int c_head_dil[12][3] = {
  {1,2,4},{1,1,1},{4,8,16},{8,16,32},{32,64,128},{64,128,256},
  {256,512,1024},{1,100,200},{1,500,1000},{1,1024,2048},{3,9,27},{5,25,125}
};

__device__ __forceinline__ float sigmoidf_(float x){ return 1.f/(1.f+__expf(-x)); }
__device__ __forceinline__ float f2tf32(float f){
    uint32_t r; asm("cvt.rna.tf32.f32 %0,%1;" : "=r"(r) : "f"(f));
    return __uint_as_float(r);
}
__device__ __forceinline__ uint32_t smem_u32(const void* p){
    uint32_t a;
    asm("{ .reg .u64 t; cvta.to.shared.u64 t, %1; cvt.u32.u64 %0, t; }" : "=r"(a) : "l"(p));
    return a;
}
__device__ __forceinline__ void cpasync16(uint32_t s, const void* g){
    asm volatile("cp.async.cg.shared.global [%0], [%1], 16;" :: "r"(s), "l"(g));
}
__device__ __forceinline__ void cpasync16z(uint32_t s, const void* g){
    asm volatile("cp.async.cg.shared.global [%0], [%1], 16, 0;" :: "r"(s), "l"(g));
}

// ---------------- weight preps ----------------
__global__ void round_copy(const float* __restrict__ in, float* __restrict__ out, int n)
{
    int i = blockIdx.x*256 + threadIdx.x;
    if (i < n) out[i] = f2tf32(in[i]);
}

// column pair-interleave + rna round: out[k][2m]=in[k][m], out[k][2m+1]=in[k][half+m]
__global__ void permute_pair(const float* __restrict__ in, float* __restrict__ out, long total, int N)
{
    long idx = (long)blockIdx.x*256 + threadIdx.x;
    if (idx >= total) return;
    long k = idx / N;
    int  j = (int)(idx % N);
    int  h = N >> 1;
    out[idx] = f2tf32(in[k*N + ((j & 1) ? h + (j >> 1) : (j >> 1))]);
}

// conv weight transpose to tap-major (fp32, not a GEMM operand)
__global__ void wtrans_kernel(const float* __restrict__ cs_w, const float* __restrict__ head_w,
                              float* __restrict__ cs_wt, float* __restrict__ head_wt)
{
    int idx = blockIdx.x*256 + threadIdx.x;
    if (idx < 6*4*1152){
        int i = idx / (4*1152);
        int r = idx % (4*1152);
        int j = r / 1152;
        int c = r % 1152;
        cs_wt[idx] = cs_w[(i*1152 + c)*4 + j];
    }
    if (idx < 36*4*96){
        int hl = idx / (4*96);
        int r  = idx % (4*96);
        int j  = r / 96;
        int c  = r % 96;
        head_wt[idx] = head_w[(hl*96 + c)*4 + j];
    }
}

// ---------------- fused rmsnorm + token scalar gate (float4, tf32-rounded out) ----------------
__global__ void rms_gate_kernel(const float* __restrict__ x, const float* __restrict__ nw,
                                const float* __restrict__ gw, const float* __restrict__ gb,
                                float* __restrict__ xn, float* __restrict__ gate)
{
    __shared__ float s1[8], s2[8], sinv;
    int t = blockIdx.x;
    const float4* xr = (const float4*)(x + (long)t*HDIM);
    const float4* gw4 = (const float4*)gw;
    const float4* nw4 = (const float4*)nw;
    float4 vbuf[2];
    float ss=0.f, dg=0.f;
    int nit = 0;
    for (int c=threadIdx.x; c<H4; c+=256){
        float4 v = xr[c]; vbuf[nit++] = v;
        float4 w = gw4[c];
        ss += v.x*v.x + v.y*v.y + v.z*v.z + v.w*v.w;
        dg += v.x*w.x + v.y*w.y + v.z*w.z + v.w*w.w;
    }
    for (int o=16;o;o>>=1){ ss+=__shfl_down_sync(~0u,ss,o); dg+=__shfl_down_sync(~0u,dg,o); }
    int w=threadIdx.x>>5, l=threadIdx.x&31;
    if (l==0){ s1[w]=ss; s2[w]=dg; }
    __syncthreads();
    if (threadIdx.x==0){
        float a=0,bq=0;
        #pragma unroll
        for (int i=0;i<8;i++){ a+=s1[i]; bq+=s2[i]; }
        sinv = rsqrtf(a/(float)HDIM + 1e-6f);
        gate[t] = 1.f/(1.f+expf(-(bq+gb[0])));
    }
    __syncthreads();
    float inv = sinv;
    float4* xo = (float4*)(xn + (long)t*HDIM);
    nit = 0;
    for (int c=threadIdx.x; c<H4; c+=256){
        float4 v = vbuf[nit++];
        float4 nwv = nw4[c];
        xo[c] = make_float4(f2tf32(v.x*inv*nwv.x), f2tf32(v.y*inv*nwv.y),
                            f2tf32(v.z*inv*nwv.z), f2tf32(v.w*inv*nwv.w));
    }
}

// ---------------- conv stack layer (float4, tap-major weights) ----------------
__global__ void conv_cs_kernel(const float4* __restrict__ in, float4* __restrict__ out,
                               const float* __restrict__ wt, const float4* __restrict__ bias4,
                               int d, int rnd)
{
    int idx = blockIdx.x*256 + threadIdx.x;
    if (idx >= TOTAL/4) return;
    int c4 = idx % H4;
    int t  = idx / H4;
    int s  = t & (SEQ-1);
    float4 wj[4];
    #pragma unroll
    for (int j=0;j<4;j++) wj[j] = ((const float4*)(wt + j*HDIM))[c4];
    float4 b4 = bias4[c4];
    float acc[4] = {b4.x, b4.y, b4.z, b4.w};
    #pragma unroll
    for (int j=0;j<4;j++){
        int sp = s - (3-j)*d;
        if (sp >= 0){
            float4 xv = in[idx + (sp - s)*H4];
            acc[0] += wj[j].x*xv.x;
            acc[1] += wj[j].y*xv.y;
            acc[2] += wj[j].z*xv.z;
            acc[3] += wj[j].w*xv.w;
        }
    }
    float4 iv = in[idx];
    float4 ov;
    ov.x = iv.x + 0.5f*acc[0]*(1.f + erff(acc[0]*0.70710678118654752f));
    ov.y = iv.y + 0.5f*acc[1]*(1.f + erff(acc[1]*0.70710678118654752f));
    ov.z = iv.z + 0.5f*acc[2]*(1.f + erff(acc[2]*0.70710678118654752f));
    ov.w = iv.w + 0.5f*acc[3]*(1.f + erff(acc[3]*0.70710678118654752f));
    if (rnd){ ov.x=f2tf32(ov.x); ov.y=f2tf32(ov.y); ov.z=f2tf32(ov.z); ov.w=f2tf32(ov.w); }
    out[idx] = ov;
}

// ---------------- head conv layer (float4, tap-major weights) ----------------
__global__ void conv_head_kernel(const float4* __restrict__ in, float4* __restrict__ out,
                                 const float* __restrict__ hwt, const float* __restrict__ hb, int layer)
{
    int idx = blockIdx.x*256 + threadIdx.x;
    if (idx >= TOTAL/4) return;
    int c4 = idx % H4;
    int t  = idx / H4;
    int s  = t & (SEQ-1);
    int ch = c4*4;
    int head = ch / HDH;
    int cin  = ch % HDH;
    int d = c_head_dil[head][layer];
    int hl = head*3 + layer;
    float4 wj[4];
    #pragma unroll
    for (int j=0;j<4;j++) wj[j] = ((const float4*)(hwt + (hl*4 + j)*HDH))[cin>>2];
    float4 b4 = ((const float4*)hb)[(hl*HDH + cin)>>2];
    float acc[4] = {b4.x, b4.y, b4.z, b4.w};
    #pragma unroll
    for (int j=0;j<4;j++){
        int sp = s - (3-j)*d;
        if (sp >= 0){
            float4 xv = in[idx + (sp - s)*H4];
            acc[0] += wj[j].x*xv.x;
            acc[1] += wj[j].y*xv.y;
            acc[2] += wj[j].z*xv.z;
            acc[3] += wj[j].w*xv.w;
        }
    }
    float4 iv = in[idx];
    out[idx] = make_float4(iv.x+acc[0], iv.y+acc[1], iv.z+acc[2], iv.w+acc[3]);
}

// ---------------- hw mul (float4, tf32-rounded out) ----------------
__global__ void hwmul_kernel(float4* __restrict__ a, const float* __restrict__ hw)
{
    int idx = blockIdx.x*256 + threadIdx.x;
    if (idx >= TOTAL/4) return;
    int t = idx / H4, h = (idx % H4)*4/HDH;
    float g = hw[t*12 + h];
    float4 v = a[idx];
    a[idx] = make_float4(f2tf32(v.x*g), f2tf32(v.y*g), f2tf32(v.z*g), f2tf32(v.w*g));
}

// ---------------- memory-head gate g and chunk means ----------------
__global__ void memg_kernel(const float* __restrict__ xg, const float* __restrict__ gw,
                            const float* __restrict__ gb, float* __restrict__ g)
{
    int t = blockIdx.x;
    int warp = threadIdx.x >> 5, lane = threadIdx.x & 31;
    const float* xr = xg + (long)t*HDIM + (6+warp)*HDH;
    const float* w  = gw + warp*HDH;
    float acc = 0.f;
    for (int c=lane;c<HDH;c+=32) acc += xr[c]*w[c];
    for (int o=16;o;o>>=1) acc += __shfl_down_sync(~0u,acc,o);
    if (lane==0) g[t*NMH+warp] = 1.f/(1.f+expf(-(acc + gb[warp])));
}

__global__ void ga_kernel(const float* __restrict__ g, float* __restrict__ ga)
{
    int e = blockIdx.x*256 + threadIdx.x;
    if (e >= 4*32*NMH) return;
    int n = e % NMH, ch = (e/NMH) % 32, b = e/(NMH*32);
    int base = (b*SEQ + ch*64)*NMH + n;
    float s = 0.f;
    for (int i=0;i<64;i++) s += g[base + i*NMH];
    ga[e] = s*(1.f/64.f);
}

// ---------------- chunked fast-weight scan (register-tiled, rounded reads) ----------------
__global__ void scan_kernel(const float* __restrict__ q, const float* __restrict__ kk,
                            const float* __restrict__ v, const float* __restrict__ g,
                            const float* __restrict__ ga, float* __restrict__ reads)
{
    extern __shared__ float smx[];
    float* sM = smx;             // 96*32
    float* sQ = sM + 96*32;      // 64*96
    float* sK = sQ + 64*96;      // 64*96
    float* sV = sK + 64*96;      // 64*32
    float4* sM4 = (float4*)sM;
    float4* sV4 = (float4*)sV;
    int bn = blockIdx.x;
    int b = bn >> 2, n = bn & 3;
    int m0 = blockIdx.y * 32;
    int tid = threadIdx.x;
    const int dd0 = (tid >> 3) * 3;
    const int mg  = tid & 7;

    for (int i=tid;i<96*32;i+=256) sM[i]=0.f;
    __syncthreads();
    for (int ch=0; ch<32; ch++){
        int tok0 = b*SEQ + ch*64;
        for (int i=tid; i<64*24; i+=256){
            int s = i/24, cc = i%24;
            long base = (long)(tok0+s)*(NMH*HDH) + n*HDH;
            float gv = g[(tok0+s)*NMH + n];
            float4 qv = ((const float4*)(q + base))[cc];
            float4 kv = ((const float4*)(kk + base))[cc];
            ((float4*)sQ)[i] = qv;
            ((float4*)sK)[i] = make_float4(kv.x*gv, kv.y*gv, kv.z*gv, kv.w*gv);
        }
        for (int i=tid; i<64*8; i+=256){
            int s = i/8, mm = i%8;
            sV4[i] = ((const float4*)(v + (long)(tok0+s)*(NMH*MDH) + n*MDH + m0))[mm];
        }
        __syncthreads();
        #pragma unroll
        for (int it=0; it<2; it++){
            int item = tid + it*256;
            int s = item >> 3, mgg = item & 7;
            const float* qs = sQ + s*96;
            float4 acc = make_float4(0.f,0.f,0.f,0.f);
            #pragma unroll 4
            for (int dd=0; dd<96; dd++){
                float qv = qs[dd];
                float4 mv = sM4[dd*8 + mgg];
                acc.x += qv*mv.x; acc.y += qv*mv.y; acc.z += qv*mv.z; acc.w += qv*mv.w;
            }
            acc.x=f2tf32(acc.x); acc.y=f2tf32(acc.y); acc.z=f2tf32(acc.z); acc.w=f2tf32(acc.w);
            ((float4*)(reads + (long)(tok0+s)*(NMH*MDH) + n*MDH + m0))[mgg] = acc;
        }
        __syncthreads();
        float gav = ga[(b*32+ch)*NMH + n];
        float om = 1.f - gav;
        float4 a0 = sM4[(dd0+0)*8+mg];
        float4 a1 = sM4[(dd0+1)*8+mg];
        float4 a2 = sM4[(dd0+2)*8+mg];
        a0.x*=om; a0.y*=om; a0.z*=om; a0.w*=om;
        a1.x*=om; a1.y*=om; a1.z*=om; a1.w*=om;
        a2.x*=om; a2.y*=om; a2.z*=om; a2.w*=om;
        __syncthreads();
        #pragma unroll 2
        for (int s=0;s<64;s++){
            const float* ks = sK + s*96 + dd0;
            float k0 = ks[0], k1 = ks[1], k2 = ks[2];
            float4 vv = sV4[s*8+mg];
            a0.x += k0*vv.x; a0.y += k0*vv.y; a0.z += k0*vv.z; a0.w += k0*vv.w;
            a1.x += k1*vv.x; a1.y += k1*vv.y; a1.z += k1*vv.z; a1.w += k1*vv.w;
            a2.x += k2*vv.x; a2.y += k2*vv.y; a2.z += k2*vv.z; a2.w += k2*vv.w;
        }
        sM4[(dd0+0)*8+mg] = a0;
        sM4[(dd0+1)*8+mg] = a1;
        sM4[(dd0+2)*8+mg] = a2;
        __syncthreads();
    }
}

// ---------------- SIMT fp32 GEMM (router, N=12) ----------------
template<bool BIAS, bool ACC, int ACT>
__global__ __launch_bounds__(256) void sgemm(
    const float* __restrict__ A, const float* __restrict__ B,
    const float* __restrict__ bias, float* __restrict__ C,
    int M, int N, int K, int lda, int ldb, int ldc,
    long sA, long sB, long sC)
{
    __shared__ __align__(16) float As[8*128];
    __shared__ __align__(16) float Bs[8*128];
    A += (long)blockIdx.z * sA;
    B += (long)blockIdx.z * sB;
    C += (long)blockIdx.z * sC;
    int tid = threadIdx.x;
    int row0 = blockIdx.y * 128;
    int col0 = blockIdx.x * 128;
    int tr4 = (tid >> 4) * 4;
    int tc4 = (tid & 15) * 4;
    int arow = tid >> 1, acol = (tid & 1) * 4;
    int brow = tid >> 5, bcol = (tid & 31) * 4;
    const float* Aptr = A + (long)(row0 + arow)*lda + acol;
    const float* Bptr = B + (long)brow*ldb + col0 + bcol;
    bool bvalid = (col0 + bcol + 3) < N;
    float acc[8][8];
    #pragma unroll
    for (int i=0;i<8;i++)
        #pragma unroll
        for (int j=0;j<8;j++) acc[i][j]=0.f;

    for (int k0=0;k0<K;k0+=8){
        float4 av = *(const float4*)Aptr;
        As[(acol+0)*128 + arow]=av.x;
        As[(acol+1)*128 + arow]=av.y;
        As[(acol+2)*128 + arow]=av.z;
        As[(acol+3)*128 + arow]=av.w;
        float4 bv = bvalid ? *(const float4*)Bptr : make_float4(0.f,0.f,0.f,0.f);
        *(float4*)&Bs[brow*128 + bcol] = bv;
        __syncthreads();
        #pragma unroll
        for (int k=0;k<8;k++){
            float4 a0 = *(const float4*)&As[k*128 + tr4];
            float4 a1 = *(const float4*)&As[k*128 + tr4 + 64];
            float4 b0 = *(const float4*)&Bs[k*128 + tc4];
            float4 b1 = *(const float4*)&Bs[k*128 + tc4 + 64];
            float ra[8] = {a0.x,a0.y,a0.z,a0.w,a1.x,a1.y,a1.z,a1.w};
            float rb[8] = {b0.x,b0.y,b0.z,b0.w,b1.x,b1.y,b1.z,b1.w};
            #pragma unroll
            for (int i=0;i<8;i++)
                #pragma unroll
                for (int j=0;j<8;j++) acc[i][j] += ra[i]*rb[j];
        }
        __syncthreads();
        Aptr += 8;
        Bptr += 8*(long)ldb;
    }
    #pragma unroll
    for (int i=0;i<8;i++){
        int r = row0 + tr4 + (i<4 ? i : i-4+64);
        #pragma unroll
        for (int j=0;j<8;j++){
            int cN = col0 + tc4 + (j<4 ? j : j-4+64);
            if (cN < N){
                float v = acc[i][j];
                if (BIAS) v += bias[cN];
                if (ACC)  v += C[(long)r*ldc + cN];
                if (ACT==1) v = 1.f/(1.f+expf(-v));
                C[(long)r*ldc + cN] = v;
            }
        }
    }
}

// ---------------- tf32 tensor-core GEMM (proven fragment core, cp.async 3-stage) ----------------
// Operands A,B must be pre-rounded to tf32 (rna).
// EPI: 0 plain, 1 resid C=E+gate[r]*(acc+bias), 2 mulsig C=round(E*sig(acc+bias)),
//      3 C+=acc, 4 GLU pairs: C[r][cN/2] = round(acc_even*sig(acc_odd)) (ldc=N/2)
#define AST 20
#define BST 136
#define SFT (128*AST + 16*BST)   // 4736 floats per stage
template<bool BIAS, int EPI>
__global__ __launch_bounds__(256) void tgemm(
    const float* __restrict__ A, const float* __restrict__ B,
    const float* __restrict__ bias, float* __restrict__ C,
    const float* __restrict__ E, const float* __restrict__ gate,
    int M, int N, int K, int lda, int ldb, int ldc,
    long sA, long sB, long sC)
{
    extern __shared__ __align__(16) float smg[];

    A += (long)blockIdx.z * sA;
    B += (long)blockIdx.z * sB;
    C += (long)blockIdx.z * sC;
    if (EPI == 1 || EPI == 2) E += (long)blockIdx.z * sC;

    const int tid  = threadIdx.x;
    const int lane = tid & 31;
    const int wid  = tid >> 5;
    const int wm   = (wid >> 2) * 64;
    const int wn   = (wid & 3) * 32;
    const int qr   = lane >> 2;
    const int qc   = lane & 3;

    const int row0 = blockIdx.y * 128;
    const int col0 = blockIdx.x * 128;

    const int ar = tid >> 2;
    const int ac = (tid & 3) * 4;
    const int bk = tid >> 5;
    const int bn = lane * 4;
    const bool bok = (col0 + bn + 3) < N;

    float acc[4][4][4];
    #pragma unroll
    for (int i=0;i<4;i++)
        #pragma unroll
        for (int j=0;j<4;j++)
            #pragma unroll
            for (int e=0;e<4;e++) acc[i][j][e]=0.f;

    const int nt = K >> 4;

    auto issue = [&](int t){
        float* as = smg + (t%3)*SFT;
        float* bs = as + 128*AST;
        const int kb = t*16;
        const float* Ag = A + (long)(row0 + ar)*lda + kb + ac;
        cpasync16(smem_u32(as + ar*AST + ac), Ag);
        cpasync16(smem_u32(as + (ar+64)*AST + ac), Ag + 64*(long)lda);
        const float* Bg = B + (long)(kb + bk)*ldb + col0 + bn;
        if (bok){
            cpasync16(smem_u32(bs + bk*BST + bn), Bg);
            cpasync16(smem_u32(bs + (bk+8)*BST + bn), Bg + 8*(long)ldb);
        } else {
            cpasync16z(smem_u32(bs + bk*BST + bn), B);
            cpasync16z(smem_u32(bs + (bk+8)*BST + bn), B);
        }
        asm volatile("cp.async.commit_group;" ::: "memory");
    };

    issue(0);
    if (nt > 1) issue(1);

    for (int t=0; t<nt; t++){
        if (t+1 < nt) asm volatile("cp.async.wait_group 1;" ::: "memory");
        else          asm volatile("cp.async.wait_group 0;" ::: "memory");
        __syncthreads();
        if (t+2 < nt) issue(t+2);    // into buffer freed by stage t-1
        const float* as = smg + (t%3)*SFT;
        const float* bs = as + 128*AST;
        #pragma unroll
        for (int ks=0; ks<2; ks++){
            uint32_t af[4][4], bf[4][2];
            #pragma unroll
            for (int i=0;i<4;i++){
                int rbase = (wm + i*16 + qr)*AST + ks*8 + qc;
                af[i][0] = __float_as_uint(as[rbase]);
                af[i][1] = __float_as_uint(as[rbase + 8*AST]);
                af[i][2] = __float_as_uint(as[rbase + 4]);
                af[i][3] = __float_as_uint(as[rbase + 8*AST + 4]);
            }
            #pragma unroll
            for (int j=0;j<4;j++){
                int cb = wn + j*8 + qr;
                bf[j][0] = __float_as_uint(bs[(ks*8 + qc)*BST + cb]);
                bf[j][1] = __float_as_uint(bs[(ks*8 + qc + 4)*BST + cb]);
            }
            #pragma unroll
            for (int i=0;i<4;i++)
                #pragma unroll
                for (int j=0;j<4;j++){
                    asm volatile(
                        "mma.sync.aligned.m16n8k8.row.col.f32.tf32.tf32.f32 "
                        "{%0,%1,%2,%3},{%4,%5,%6,%7},{%8,%9},{%0,%1,%2,%3};"
                        : "+f"(acc[i][j][0]), "+f"(acc[i][j][1]),
                          "+f"(acc[i][j][2]), "+f"(acc[i][j][3])
                        : "r"(af[i][0]), "r"(af[i][1]), "r"(af[i][2]), "r"(af[i][3]),
                          "r"(bf[j][0]), "r"(bf[j][1]));
                }
        }
    }

    // epilogue
    #pragma unroll
    for (int i=0;i<4;i++){
        int r0 = row0 + wm + i*16 + qr;
        float gg0 = 0.f, gg1 = 0.f;
        if (EPI == 1){ gg0 = gate[r0]; gg1 = gate[r0+8]; }
        #pragma unroll
        for (int j=0;j<4;j++){
            int cN = col0 + wn + j*8 + qc*2;
            if (cN < N){
                float bv0 = BIAS ? bias[cN]   : 0.f;
                float bv1 = BIAS ? bias[cN+1] : 0.f;
                float v0 = acc[i][j][0] + bv0;
                float v1 = acc[i][j][1] + bv1;
                float v2 = acc[i][j][2] + bv0;
                float v3 = acc[i][j][3] + bv1;
                if (EPI == 4){
                    long p0 = (long)r0*ldc + (cN>>1);
                    long p1 = (long)(r0+8)*ldc + (cN>>1);
                    C[p0] = f2tf32(v0*sigmoidf_(v1));
                    C[p1] = f2tf32(v2*sigmoidf_(v3));
                } else {
                    long o00 = (long)r0*ldc + cN;
                    long o10 = (long)(r0+8)*ldc + cN;
                    if (EPI == 1){
                        v0 = E[o00]   + gg0*v0;
                        v1 = E[o00+1] + gg0*v1;
                        v2 = E[o10]   + gg1*v2;
                        v3 = E[o10+1] + gg1*v3;
                    } else if (EPI == 2){
                        v0 = f2tf32(E[o00]  *sigmoidf_(v0));
                        v1 = f2tf32(E[o00+1]*sigmoidf_(v1));
                        v2 = f2tf32(E[o10]  *sigmoidf_(v2));
                        v3 = f2tf32(E[o10+1]*sigmoidf_(v3));
                    } else if (EPI == 3){
                        v0 += C[o00]; v1 += C[o00+1]; v2 += C[o10]; v3 += C[o10+1];
                    }
                    C[o00]   = v0;
                    C[o00+1] = v1;
                    C[o10]   = v2;
                    C[o10+1] = v3;
                }
            }
        }
    }
}

// ---------------- host ----------------
extern "C" void kernel_launch(void* const* d_in, const int* in_sizes, int n_in,
                              void* d_out, int out_size)
{
    const float* x          = (const float*)d_in[0];
    const float* norm1_w    = (const float*)d_in[1];
    const float* norm2_w    = (const float*)d_in[2];
    const float* norm3_w    = (const float*)d_in[3];
    const float* cs_w       = (const float*)d_in[4];
    const float* cs_b       = (const float*)d_in[5];
    const float* cs_proj_w  = (const float*)d_in[6];
    const float* cs_proj_b  = (const float*)d_in[7];
    const float* gate_proj_w= (const float*)d_in[8];
    const float* router_w   = (const float*)d_in[9];
    const float* router_b   = (const float*)d_in[10];
    const float* head_w     = (const float*)d_in[11];
    const float* head_b     = (const float*)d_in[12];
    const float* mem_q      = (const float*)d_in[13];
    const float* mem_k      = (const float*)d_in[14];
    const float* mem_v      = (const float*)d_in[15];
    const float* mem_gw     = (const float*)d_in[16];
    const float* mem_gb     = (const float*)d_in[17];
    const float* mem_out    = (const float*)d_in[18];
    const float* mixgate_w  = (const float*)d_in[19];
    const float* mixgate_b  = (const float*)d_in[20];
    const float* mixing_w   = (const float*)d_in[21];
    const float* mixing_b   = (const float*)d_in[22];
    const float* ffn_in_w   = (const float*)d_in[23];
    const float* ffn_out_w  = (const float*)d_in[24];
    const float* cg_w       = (const float*)d_in[25];
    const float* cg_b       = (const float*)d_in[26];
    const float* sg_w       = (const float*)d_in[27];
    const float* sg_b       = (const float*)d_in[28];
    const float* fg_w       = (const float*)d_in[29];
    const float* fg_b       = (const float*)d_in[30];

    float *X,*A,*Bb,*C,*D,*GLU,*Q,*Kb,*V,*R,*G,*GA,*GATE,*HW,*WPGP,*WPFI,*CSWT,*HDWT;
    float *WCS,*WMG,*WMX,*WFO,*WMQ,*WMK,*WMV,*WMO;
    cudaGetSymbolAddress((void**)&X,  g_x);
    cudaGetSymbolAddress((void**)&A,  g_a);
    cudaGetSymbolAddress((void**)&Bb, g_b);
    cudaGetSymbolAddress((void**)&C,  g_c);
    cudaGetSymbolAddress((void**)&D,  g_d);
    cudaGetSymbolAddress((void**)&GLU,g_glu);
    cudaGetSymbolAddress((void**)&Q,  g_q);
    cudaGetSymbolAddress((void**)&Kb, g_k);
    cudaGetSymbolAddress((void**)&V,  g_v);
    cudaGetSymbolAddress((void**)&R,  g_r);
    cudaGetSymbolAddress((void**)&G,  g_g);
    cudaGetSymbolAddress((void**)&GA, g_ga);
    cudaGetSymbolAddress((void**)&GATE,g_gate);
    cudaGetSymbolAddress((void**)&HW, g_hw);
    cudaGetSymbolAddress((void**)&WPGP, g_wp_gp);
    cudaGetSymbolAddress((void**)&WPFI, g_wp_fi);
    cudaGetSymbolAddress((void**)&CSWT, g_cs_wt);
    cudaGetSymbolAddress((void**)&HDWT, g_hd_wt);
    cudaGetSymbolAddress((void**)&WCS, g_w_cs);
    cudaGetSymbolAddress((void**)&WMG, g_w_mg);
    cudaGetSymbolAddress((void**)&WMX, g_w_mx);
    cudaGetSymbolAddress((void**)&WFO, g_w_fo);
    cudaGetSymbolAddress((void**)&WMQ, g_w_mq);
    cudaGetSymbolAddress((void**)&WMK, g_w_mk);
    cudaGetSymbolAddress((void**)&WMV, g_w_mv);
    cudaGetSymbolAddress((void**)&WMO, g_w_mo);

    const int TGSM = 3*SFT*4;   // 56832 bytes
    cudaFuncSetAttribute(scan_kernel, cudaFuncAttributeMaxDynamicSharedMemorySize, 69632);
    cudaFuncSetAttribute(tgemm<true,1>,  cudaFuncAttributeMaxDynamicSharedMemorySize, TGSM);
    cudaFuncSetAttribute(tgemm<false,0>, cudaFuncAttributeMaxDynamicSharedMemorySize, TGSM);
    cudaFuncSetAttribute(tgemm<false,4>, cudaFuncAttributeMaxDynamicSharedMemorySize, TGSM);
    cudaFuncSetAttribute(tgemm<false,3>, cudaFuncAttributeMaxDynamicSharedMemorySize, TGSM);
    cudaFuncSetAttribute(tgemm<true,2>,  cudaFuncAttributeMaxDynamicSharedMemorySize, TGSM);
    cudaFuncSetAttribute(tgemm<false,1>, cudaFuncAttributeMaxDynamicSharedMemorySize, TGSM);

    const int EB4 = TOTAL/4/256;   // 9216

    // ===== weight preps =====
    permute_pair<<<(1152L*2304+255)/256,256>>>(gate_proj_w, WPGP, 1152L*2304, 2304);
    permute_pair<<<(1152L*9216+255)/256,256>>>(ffn_in_w,  WPFI, 1152L*9216, 9216);
    wtrans_kernel<<<108,256>>>(cs_w, head_w, CSWT, HDWT);
    round_copy<<<(1152*1152+255)/256,256>>>(cs_proj_w, WCS, 1152*1152);
    round_copy<<<(1152*1152+255)/256,256>>>(mixgate_w, WMG, 1152*1152);
    round_copy<<<(1152*1152+255)/256,256>>>(mixing_w,  WMX, 1152*1152);
    round_copy<<<(4608*1152+255)/256,256>>>(ffn_out_w, WFO, 4608*1152);
    round_copy<<<(4*96*96+255)/256,256>>>(mem_q,   WMQ, 4*96*96);
    round_copy<<<(4*96*96+255)/256,256>>>(mem_k,   WMK, 4*96*96);
    round_copy<<<(4*96*128+255)/256,256>>>(mem_v,  WMV, 4*96*128);
    round_copy<<<(4*128*96+255)/256,256>>>(mem_out,WMO, 4*128*96);

    // ===== stage 1: conv stack =====
    rms_gate_kernel<<<NTOK,256>>>(x, norm1_w, cg_w, cg_b, A, GATE);
    {
        const int dil[6] = {1,2,4,8,16,32};
        float* pin = A; float* pout = Bb;
        for (int i=0;i<6;i++){
            conv_cs_kernel<<<EB4,256>>>((const float4*)pin, (float4*)pout,
                CSWT + i*4*HDIM, (const float4*)(cs_b + i*HDIM), dil[i], i==5);
            float* tmp = pin; pin = pout; pout = tmp;
        }
    }
    // X = x + gate*(A@cs_proj + b)
    tgemm<true,1><<<dim3(9,64,1),256,TGSM>>>(A, WCS, cs_proj_b, X, x, GATE,
        NTOK, HDIM, HDIM, HDIM, HDIM, HDIM, 0,0,0);

    // ===== stage 2: multi-head state =====
    rms_gate_kernel<<<NTOK,256>>>(X, norm2_w, sg_w, sg_b, A, GATE);
    sgemm<true,false,1><<<dim3(1,64,1),256>>>(A, router_w, router_b, HW,
        NTOK, 12, HDIM, HDIM, 12, 12, 0,0,0);
    // Bb = glu(A @ gate_proj)  (fused via pair-interleaved weights)
    tgemm<false,4><<<dim3(18,64,1),256,TGSM>>>(A, WPGP, nullptr, Bb, nullptr, nullptr,
        NTOK, 2304, HDIM, HDIM, 2304, HDIM, 0,0,0);
    memg_kernel<<<NTOK,128>>>(Bb, mem_gw, mem_gb, G);
    ga_kernel<<<2,256>>>(G, GA);
    tgemm<false,0><<<dim3(1,64,4),256,TGSM>>>(Bb + 6*HDH, WMQ, nullptr, Q, nullptr, nullptr,
        NTOK, HDH, HDH, HDIM, HDH, NMH*HDH, HDH, HDH*HDH, HDH);
    tgemm<false,0><<<dim3(1,64,4),256,TGSM>>>(Bb + 6*HDH, WMK, nullptr, Kb, nullptr, nullptr,
        NTOK, HDH, HDH, HDIM, HDH, NMH*HDH, HDH, HDH*HDH, HDH);
    tgemm<false,0><<<dim3(1,64,4),256,TGSM>>>(Bb + 6*HDH, WMV, nullptr, V, nullptr, nullptr,
        NTOK, MDH, HDH, HDIM, MDH, NMH*MDH, HDH, HDH*MDH, MDH);
    conv_head_kernel<<<EB4,256>>>((const float4*)Bb, (float4*)C, HDWT, head_b, 0);
    conv_head_kernel<<<EB4,256>>>((const float4*)C,  (float4*)A, HDWT, head_b, 1);
    conv_head_kernel<<<EB4,256>>>((const float4*)A,  (float4*)C, HDWT, head_b, 2);
    scan_kernel<<<dim3(16,4),256,69632>>>(Q, Kb, V, G, GA, R);
    // C[:, memheads] += R @ mem_out
    tgemm<false,3><<<dim3(1,64,4),256,TGSM>>>(R, WMO, nullptr, C + 6*HDH, nullptr, nullptr,
        NTOK, HDH, MDH, NMH*MDH, HDH, HDIM, MDH, MDH*HDH, HDH);
    hwmul_kernel<<<EB4,256>>>((float4*)C, HW);
    // D = round(C * sigmoid(C@mixgate + b))
    tgemm<true,2><<<dim3(9,64,1),256,TGSM>>>(C, WMG, mixgate_b, D, C, nullptr,
        NTOK, HDIM, HDIM, HDIM, HDIM, HDIM, 0,0,0);
    // X = X + gate*(D@mixing + b)
    tgemm<true,1><<<dim3(9,64,1),256,TGSM>>>(D, WMX, mixing_b, X, X, GATE,
        NTOK, HDIM, HDIM, HDIM, HDIM, HDIM, 0,0,0);

    // ===== stage 3: GLU FFN =====
    rms_gate_kernel<<<NTOK,256>>>(X, norm3_w, fg_w, fg_b, A, GATE);
    // GLU = glu(A @ ffn_in)  (fused)
    tgemm<false,4><<<dim3(72,64,1),256,TGSM>>>(A, WPFI, nullptr, GLU, nullptr, nullptr,
        NTOK, 9216, HDIM, HDIM, 9216, INNERD, 0,0,0);
    // out = X + gate*(GLU@ffn_out)
    tgemm<false,1><<<dim3(9,64,1),256,TGSM>>>(GLU, WFO, nullptr, (float*)d_out, X, GATE,
        NTOK, HDIM, INNERD, INNERD, HDIM, HDIM, 0,0,0);

    (void)in_sizes; (void)n_in; (void)out_size;
}